// round 8
// baseline (speedup 1.0000x reference)
#include <cuda_runtime.h>
#include <cuda_bf16.h>
#include <math.h>
#include <stdint.h>

#define NN    30000
#define NE    960000
#define ET    (NE + NN)
#define INDIM 4527
#define KPAD1 4544
#define HOGD  4464
#define HID   128
#define NG    64

// ---------------- scratch (device globals) ----------------------------------
__device__ float g_h1[NN * 256];
__device__ float g_as1[NN * 2];
__device__ float g_ad1[NN * 2];
__device__ float g_h2[NN * HID];
__device__ float g_as2[NN];
__device__ float g_ad2[NN];
__device__ int   g_cntN[NN];
__device__ int   g_indptr[NN + 1];
__device__ int   g_cursor[NN];
__device__ int   g_srcs[ET];
__device__ float g_pool[NG * HID];
__device__ int   g_gcnt[NG];
// pre-split bf16 operands (+128 row slack so OOB tile loads stay in-bounds)
__device__ __nv_bfloat16 g_xhi[(NN + 128) * KPAD1];
__device__ __nv_bfloat16 g_xlo[(NN + 128) * KPAD1];
__device__ __nv_bfloat16 g_a1hi[(NN + 128) * 256];
__device__ __nv_bfloat16 g_a1lo[(NN + 128) * 256];
__device__ __nv_bfloat16 g_W1Thi[256 * KPAD1];
__device__ __nv_bfloat16 g_W1Tlo[256 * KPAD1];
__device__ __nv_bfloat16 g_W2Thi[128 * 256];
__device__ __nv_bfloat16 g_W2Tlo[128 * 256];

// ---------------- helpers ---------------------------------------------------
__device__ __forceinline__ uint32_t smem_u32(const void* p) {
    uint32_t a;
    asm("{ .reg .u64 t; cvta.to.shared.u64 t, %1; cvt.u32.u64 %0, t; }"
        : "=r"(a) : "l"(p));
    return a;
}
__device__ __forceinline__ float warpSum(float v) {
#pragma unroll
    for (int o = 16; o; o >>= 1) v += __shfl_xor_sync(0xffffffffu, v, o);
    return v;
}
__device__ __forceinline__ float warpMax(float v) {
#pragma unroll
    for (int o = 16; o; o >>= 1) v = fmaxf(v, __shfl_xor_sync(0xffffffffu, v, o));
    return v;
}
__device__ __forceinline__ float lrelu(float v) { return v > 0.f ? v : 0.2f * v; }

__device__ __forceinline__ void mma16816(float c[4], const uint32_t a[4],
                                         uint32_t b0, uint32_t b1) {
    asm volatile(
        "mma.sync.aligned.m16n8k16.row.col.f32.bf16.bf16.f32 "
        "{%0,%1,%2,%3}, {%4,%5,%6,%7}, {%8,%9}, {%0,%1,%2,%3};"
        : "+f"(c[0]), "+f"(c[1]), "+f"(c[2]), "+f"(c[3])
        : "r"(a[0]), "r"(a[1]), "r"(a[2]), "r"(a[3]), "r"(b0), "r"(b1));
}
#define LDSM4(r0, r1, r2, r3, addr)                                           \
    asm volatile("ldmatrix.sync.aligned.m8n8.x4.shared.b16 {%0,%1,%2,%3}, [%4];" \
                 : "=r"(r0), "=r"(r1), "=r"(r2), "=r"(r3) : "r"(addr))
#define CP16(saddr, gaddr)                                                    \
    asm volatile("cp.async.cg.shared.global [%0], [%1], 16;"                  \
                 :: "r"(saddr), "l"(gaddr))
#define CP_COMMIT() asm volatile("cp.async.commit_group;" ::: "memory")
#define CP_WAIT1()  asm volatile("cp.async.wait_group 1;" ::: "memory")

__device__ __forceinline__ unsigned packsplit(float v0, float v1, float& r0, float& r1) {
    __nv_bfloat16 h0 = __float2bfloat16(v0), h1 = __float2bfloat16(v1);
    r0 = v0 - __bfloat162float(h0);
    r1 = v1 - __bfloat162float(h1);
    unsigned short a = *(unsigned short*)&h0, b = *(unsigned short*)&h1;
    return (unsigned)a | ((unsigned)b << 16);
}
__device__ __forceinline__ unsigned packlo(float v0, float v1) {
    __nv_bfloat16 h0 = __float2bfloat16(v0), h1 = __float2bfloat16(v1);
    unsigned short a = *(unsigned short*)&h0, b = *(unsigned short*)&h1;
    return (unsigned)a | ((unsigned)b << 16);
}

// ---------------- attention gate + split gated x + scattered init -----------
__global__ __launch_bounds__(256) void k_attn(const float* __restrict__ x,
                                              const float* __restrict__ aW,
                                              const float* __restrict__ ab) {
    int n = blockIdx.x;
    int t = threadIdx.x;  // 256
    {
        int i = n * 256 + t;
        if (i < NN) g_cntN[i] = 1;
        if (i < NG * HID) g_pool[i] = 0.f;
        if (i < NG) g_gcnt[i] = 0;
    }
    const float* xr = x + (size_t)n * INDIM;
    float p0 = 0.f, p1 = 0.f;
    for (int k = t; k < INDIM; k += 256) {
        float v = xr[k];
        p0 += v * aW[2 * k];
        p1 += v * aW[2 * k + 1];
    }
    p0 = warpSum(p0);
    p1 = warpSum(p1);
    __shared__ float s0[8], s1[8];
    __shared__ float gg[2];
    if ((t & 31) == 0) { s0[t >> 5] = p0; s1[t >> 5] = p1; }
    __syncthreads();
    if (t == 0) {
        p0 = ab[0]; p1 = ab[1];
#pragma unroll
        for (int i = 0; i < 8; i++) { p0 += s0[i]; p1 += s1[i]; }
        float m = fmaxf(p0, p1);
        float e0 = expf(p0 - m), e1 = expf(p1 - m);
        float inv = 1.f / (e0 + e1);
        gg[0] = e0 * inv;
        gg[1] = e1 * inv;
    }
    __syncthreads();
    float g0 = gg[0], g1 = gg[1];
    uint2* oh = (uint2*)(g_xhi + (size_t)n * KPAD1);
    uint2* ol = (uint2*)(g_xlo + (size_t)n * KPAD1);
    for (int p = t; p < KPAD1 / 4; p += 256) {
        int k = 4 * p;
        float v[4];
#pragma unroll
        for (int j = 0; j < 4; j++) {
            int kk = k + j;
            v[j] = (kk < INDIM) ? xr[kk] * ((kk < HOGD) ? g0 : g1) : 0.f;
        }
        float r0, r1, r2, r3;
        uint2 hi, lo;
        hi.x = packsplit(v[0], v[1], r0, r1);
        hi.y = packsplit(v[2], v[3], r2, r3);
        lo.x = packlo(r0, r1);
        lo.y = packlo(r2, r3);
        oh[p] = hi;
        ol[p] = lo;
    }
}

// ---------------- weight split (+transpose to [n][k]) -----------------------
__global__ void k_split(const float* __restrict__ W1, const float* __restrict__ W2) {
    int i = blockIdx.x * blockDim.x + threadIdx.x;
    if (i < 256 * KPAD1) {
        int n = i / KPAD1, k = i % KPAD1;
        float v = (k < INDIM) ? W1[(size_t)k * 256 + n] : 0.f;
        __nv_bfloat16 h = __float2bfloat16(v);
        g_W1Thi[i] = h;
        g_W1Tlo[i] = __float2bfloat16(v - __bfloat162float(h));
    }
    if (i < 128 * 256) {
        int n = i / 256, k = i % 256;
        float v = W2[k * 128 + n];
        __nv_bfloat16 h = __float2bfloat16(v);
        g_W2Thi[i] = h;
        g_W2Tlo[i] = __float2bfloat16(v - __bfloat162float(h));
    }
}

// ---------------- split-bf16 tensor GEMM, 3-stage swizzled pipeline ---------
// (R6-proven mainloop: cp issued right after barrier, both ks blocks after)
#define PARTB   8192
#define STAGEB  (4 * PARTB)
#define GSMEM_BYTES (3 * STAGEB + 1024)

template <int KPADT, int NTOT>
__global__ __launch_bounds__(256, 2)
void k_gemm_cp(const __nv_bfloat16* __restrict__ Ahi,
               const __nv_bfloat16* __restrict__ Alo,
               const __nv_bfloat16* __restrict__ Bhi,
               const __nv_bfloat16* __restrict__ Blo,
               float* __restrict__ C) {
    constexpr int KT = KPADT / 32;
    extern __shared__ char smraw[];
    char* smb = (char*)(((uintptr_t)smraw + 1023) & ~(uintptr_t)1023);
    const uint32_t sb = smem_u32(smb);
    const int tid = threadIdx.x;
    const int l = tid & 31, w = tid >> 5;
    const int wm = w >> 2, wn = w & 3;       // 2x4 grid, 64x32 warp tiles
    const int bn = blockIdx.x * 128;
    const int bm = blockIdx.y * 128;

    const int crow = tid >> 1;
    const int cp0 = (tid & 1) * 2;
    const int csw = (crow >> 1) & 3;
    const uint32_t cs0 = (uint32_t)(crow * 64 + ((cp0 ^ csw) * 16));
    const uint32_t cs1 = (uint32_t)(crow * 64 + (((cp0 + 1) ^ csw) * 16));
    const __nv_bfloat16* aHiP = Ahi + (size_t)(bm + crow) * KPADT + cp0 * 8;
    const __nv_bfloat16* aLoP = Alo + (size_t)(bm + crow) * KPADT + cp0 * 8;
    const __nv_bfloat16* bHiP = Bhi + (size_t)(bn + crow) * KPADT + cp0 * 8;
    const __nv_bfloat16* bLoP = Blo + (size_t)(bn + crow) * KPADT + cp0 * 8;

    float acc[4][4][4];
#pragma unroll
    for (int i = 0; i < 4; i++)
#pragma unroll
        for (int j = 0; j < 4; j++)
#pragma unroll
            for (int q = 0; q < 4; q++) acc[i][j][q] = 0.f;

    auto cpStage = [&](int kt, int s) {
        const int k0 = kt * 32;
        uint32_t d = sb + s * STAGEB;
        CP16(d + cs0,             (const char*)(aHiP + k0));
        CP16(d + cs1,             (const char*)(aHiP + k0 + 8));
        CP16(d + PARTB + cs0,     (const char*)(aLoP + k0));
        CP16(d + PARTB + cs1,     (const char*)(aLoP + k0 + 8));
        CP16(d + 2 * PARTB + cs0, (const char*)(bHiP + k0));
        CP16(d + 2 * PARTB + cs1, (const char*)(bHiP + k0 + 8));
        CP16(d + 3 * PARTB + cs0, (const char*)(bLoP + k0));
        CP16(d + 3 * PARTB + cs1, (const char*)(bLoP + k0 + 8));
    };

    const uint32_t a_roff = (uint32_t)((wm * 64 + (l & 15)) * 64);
    const int sA = ((l & 15) >> 1) & 3;
    const int aC = (l >> 4) & 1;
    const uint32_t b_rl = (uint32_t)(((l >> 4) & 1) * 8 + (l & 7));
    const uint32_t b_roff = (uint32_t)((wn * 32) * 64) + b_rl * 64;
    const int sB = (int)((b_rl >> 1) & 3);
    const int bC = (l >> 3) & 1;

    cpStage(0, 0);
    CP_COMMIT();
    cpStage(1, 1);
    CP_COMMIT();

    int s = 0;
    for (int kt = 0; kt < KT; kt++) {
        CP_WAIT1();
        __syncthreads();
        if (kt + 2 < KT) {
            int ns = s + 2; if (ns >= 3) ns -= 3;
            cpStage(kt + 2, ns);
        }
        CP_COMMIT();

        const uint32_t stb = sb + s * STAGEB;
#pragma unroll
        for (int ks = 0; ks < 2; ks++) {
            const uint32_t ca = (uint32_t)(((2 * ks + aC) ^ sA) * 16);
            const uint32_t cb = (uint32_t)(((2 * ks + bC) ^ sB) * 16);
            uint32_t ah[4][4], al[4][4];
#pragma unroll
            for (int mt = 0; mt < 4; mt++) {
                uint32_t off = a_roff + mt * 1024 + ca;
                LDSM4(ah[mt][0], ah[mt][1], ah[mt][2], ah[mt][3], stb + off);
                LDSM4(al[mt][0], al[mt][1], al[mt][2], al[mt][3],
                      stb + PARTB + off);
            }
            uint32_t bh[4][2], bl[4][2];
#pragma unroll
            for (int pr = 0; pr < 2; pr++) {
                uint32_t off = b_roff + pr * 1024 + cb;
                LDSM4(bh[2 * pr][0], bh[2 * pr][1], bh[2 * pr + 1][0],
                      bh[2 * pr + 1][1], stb + 2 * PARTB + off);
                LDSM4(bl[2 * pr][0], bl[2 * pr][1], bl[2 * pr + 1][0],
                      bl[2 * pr + 1][1], stb + 3 * PARTB + off);
            }
#pragma unroll
            for (int nt = 0; nt < 4; nt++)
#pragma unroll
                for (int mt = 0; mt < 4; mt++) {
                    mma16816(acc[mt][nt], ah[mt], bh[nt][0], bh[nt][1]);
                    mma16816(acc[mt][nt], ah[mt], bl[nt][0], bl[nt][1]);
                    mma16816(acc[mt][nt], al[mt], bh[nt][0], bh[nt][1]);
                }
        }
        if (++s == 3) s = 0;
    }

    const int g = l >> 2, tq = l & 3;
#pragma unroll
    for (int mt = 0; mt < 4; mt++)
#pragma unroll
        for (int nt = 0; nt < 4; nt++) {
            int m0 = bm + wm * 64 + mt * 16 + g;
            int n = bn + wn * 32 + nt * 8 + 2 * tq;
            if (m0 < NN)
                *(float2*)&C[(size_t)m0 * NTOT + n] =
                    make_float2(acc[mt][nt][0], acc[mt][nt][1]);
            if (m0 + 8 < NN)
                *(float2*)&C[(size_t)(m0 + 8) * NTOT + n] =
                    make_float2(acc[mt][nt][2], acc[mt][nt][3]);
        }
}

// ---------------- alpha layer 1 (float4 gathers) ----------------------------
__global__ void k_alpha1(const float* __restrict__ as1,
                         const float* __restrict__ ad1) {
    int w = (blockIdx.x * blockDim.x + threadIdx.x) >> 5;
    int l = threadIdx.x & 31;
    if (w >= NN) return;
    const float4* h4 = (const float4*)(g_h1 + (size_t)w * 256);
    const float4* as4 = (const float4*)as1;
    const float4* ad4 = (const float4*)ad1;
    float4 x0 = h4[l], x1 = h4[32 + l];
    float4 a0 = as4[l], a1 = as4[32 + l];
    float4 d0 = ad4[l], d1 = ad4[32 + l];
    float ps0 = x0.x * a0.x + x0.y * a0.y + x0.z * a0.z + x0.w * a0.w;
    float pd0 = x0.x * d0.x + x0.y * d0.y + x0.z * d0.z + x0.w * d0.w;
    float ps1 = x1.x * a1.x + x1.y * a1.y + x1.z * a1.z + x1.w * a1.w;
    float pd1 = x1.x * d1.x + x1.y * d1.y + x1.z * d1.z + x1.w * d1.w;
    ps0 = warpSum(ps0); pd0 = warpSum(pd0);
    ps1 = warpSum(ps1); pd1 = warpSum(pd1);
    if (l == 0) {
        g_as1[2 * w] = ps0; g_as1[2 * w + 1] = ps1;
        g_ad1[2 * w] = pd0; g_ad1[2 * w + 1] = pd1;
    }
}

// ---------------- CSR build --------------------------------------------------
__global__ void k_count(const int* __restrict__ ei) {
    int e = blockIdx.x * blockDim.x + threadIdx.x;
    if (e < NE) atomicAdd(&g_cntN[ei[NE + e]], 1);
}

__global__ void k_scan() {
    __shared__ int sh[1024];
    int t = threadIdx.x;
    const int CH = (NN + 1023) / 1024;
    int lo = t * CH, hi = min(lo + CH, NN);
    int s = 0;
    for (int i = lo; i < hi; i++) s += g_cntN[i];
    sh[t] = s;
    __syncthreads();
    for (int o = 1; o < 1024; o <<= 1) {
        int v = (t >= o) ? sh[t - o] : 0;
        __syncthreads();
        sh[t] += v;
        __syncthreads();
    }
    int run = (t == 0) ? 0 : sh[t - 1];
    for (int i = lo; i < hi; i++) {
        g_indptr[i] = run;
        g_srcs[run] = i;
        g_cursor[i] = 1;
        run += g_cntN[i];
    }
    if (t == 1023) g_indptr[NN] = sh[1023];
}

__global__ void k_scatter(const int* __restrict__ ei) {
    int e = blockIdx.x * blockDim.x + threadIdx.x;
    if (e < NE) {
        int s = ei[e], d = ei[NE + e];
        int pos = g_indptr[d] + atomicAdd(&g_cursor[d], 1);
        g_srcs[pos] = s;
    }
}

// ---------------- layer-1 aggregation (float4 gather, packed bf16 out) ------
__global__ void k_agg1(const float* __restrict__ b1) {
    int w = (blockIdx.x * blockDim.x + threadIdx.x) >> 5;
    int l = threadIdx.x & 31;
    if (w >= NN) return;
    int beg = g_indptr[w], end = g_indptr[w + 1];
    float ad0 = g_ad1[2 * w], ad1 = g_ad1[2 * w + 1];

    float m0 = -1e30f, m1 = -1e30f;
    for (int j = beg + l; j < end; j += 32) {
        int s = g_srcs[j];
        m0 = fmaxf(m0, lrelu(g_as1[2 * s] + ad0));
        m1 = fmaxf(m1, lrelu(g_as1[2 * s + 1] + ad1));
    }
    m0 = warpMax(m0); m1 = warpMax(m1);

    float d0 = 0.f, d1 = 0.f;
    for (int j = beg + l; j < end; j += 32) {
        int s = g_srcs[j];
        d0 += expf(lrelu(g_as1[2 * s] + ad0) - m0);
        d1 += expf(lrelu(g_as1[2 * s + 1] + ad1) - m1);
    }
    d0 = warpSum(d0); d1 = warpSum(d1);
    float i0 = 1.f / (d0 + 1e-16f), i1 = 1.f / (d1 + 1e-16f);

    float acc[8] = {0, 0, 0, 0, 0, 0, 0, 0};
    for (int base = beg; base < end; base += 32) {
        int j = base + l;
        int s = 0; float w0 = 0.f, w1 = 0.f;
        if (j < end) {
            s = g_srcs[j];
            w0 = expf(lrelu(g_as1[2 * s] + ad0) - m0) * i0;
            w1 = expf(lrelu(g_as1[2 * s + 1] + ad1) - m1) * i1;
        }
        int cnt = min(32, end - base);
        for (int q = 0; q < cnt; q++) {
            int   sq  = __shfl_sync(0xffffffffu, s, q);
            float w0q = __shfl_sync(0xffffffffu, w0, q);
            float w1q = __shfl_sync(0xffffffffu, w1, q);
            const float4* hp = (const float4*)(g_h1 + (size_t)sq * 256);
            float4 u0 = hp[l];        // head0 cols 4l..4l+3
            float4 u1 = hp[32 + l];   // head1 cols 128+4l..
            acc[0] += w0q * u0.x; acc[1] += w0q * u0.y;
            acc[2] += w0q * u0.z; acc[3] += w0q * u0.w;
            acc[4] += w1q * u1.x; acc[5] += w1q * u1.y;
            acc[6] += w1q * u1.z; acc[7] += w1q * u1.w;
        }
    }
    // bias + relu + split-bf16 packed stores (4 cols per head, consecutive)
    float v[8];
#pragma unroll
    for (int j = 0; j < 4; j++) {
        float t0 = acc[j] + b1[4 * l + j];
        float t1 = acc[4 + j] + b1[128 + 4 * l + j];
        v[j] = t0 > 0.f ? t0 : 0.f;
        v[4 + j] = t1 > 0.f ? t1 : 0.f;
    }
    float r0, r1, r2, r3;
    uint2 hi0, lo0, hi1, lo1;
    hi0.x = packsplit(v[0], v[1], r0, r1); lo0.x = packlo(r0, r1);
    hi0.y = packsplit(v[2], v[3], r2, r3); lo0.y = packlo(r2, r3);
    hi1.x = packsplit(v[4], v[5], r0, r1); lo1.x = packlo(r0, r1);
    hi1.y = packsplit(v[6], v[7], r2, r3); lo1.y = packlo(r2, r3);
    *(uint2*)(g_a1hi + (size_t)w * 256 + 4 * l)       = hi0;
    *(uint2*)(g_a1lo + (size_t)w * 256 + 4 * l)       = lo0;
    *(uint2*)(g_a1hi + (size_t)w * 256 + 128 + 4 * l) = hi1;
    *(uint2*)(g_a1lo + (size_t)w * 256 + 128 + 4 * l) = lo1;
}

// ---------------- alpha layer 2 (float4) -------------------------------------
__global__ void k_alpha2(const float* __restrict__ as2,
                         const float* __restrict__ ad2) {
    int w = (blockIdx.x * blockDim.x + threadIdx.x) >> 5;
    int l = threadIdx.x & 31;
    if (w >= NN) return;
    const float4* h4 = (const float4*)(g_h2 + (size_t)w * 128);
    const float4* as4 = (const float4*)as2;
    const float4* ad4 = (const float4*)ad2;
    float4 x = h4[l];
    float4 a = as4[l];
    float4 d = ad4[l];
    float ps = x.x * a.x + x.y * a.y + x.z * a.z + x.w * a.w;
    float pd = x.x * d.x + x.y * d.y + x.z * d.z + x.w * d.w;
    ps = warpSum(ps); pd = warpSum(pd);
    if (l == 0) { g_as2[w] = ps; g_ad2[w] = pd; }
}

// ---------------- layer-2 aggregation + pooling (float4 gather) --------------
__global__ void k_agg2(const float* __restrict__ b2,
                       const int* __restrict__ batch) {
    int w = (blockIdx.x * blockDim.x + threadIdx.x) >> 5;
    int l = threadIdx.x & 31;
    if (w >= NN) return;
    int beg = g_indptr[w], end = g_indptr[w + 1];
    float ad = g_ad2[w];

    float m = -1e30f;
    for (int j = beg + l; j < end; j += 32)
        m = fmaxf(m, lrelu(g_as2[g_srcs[j]] + ad));
    m = warpMax(m);

    float den = 0.f;
    for (int j = beg + l; j < end; j += 32)
        den += expf(lrelu(g_as2[g_srcs[j]] + ad) - m);
    den = warpSum(den);
    float inv = 1.f / (den + 1e-16f);

    float acc[4] = {0, 0, 0, 0};
    for (int base = beg; base < end; base += 32) {
        int j = base + l;
        int s = 0; float ww = 0.f;
        if (j < end) {
            s = g_srcs[j];
            ww = expf(lrelu(g_as2[s] + ad) - m) * inv;
        }
        int cnt = min(32, end - base);
        for (int q = 0; q < cnt; q++) {
            int   sq = __shfl_sync(0xffffffffu, s, q);
            float wq = __shfl_sync(0xffffffffu, ww, q);
            const float4* hp = (const float4*)(g_h2 + (size_t)sq * 128);
            float4 u = hp[l];   // cols 4l..4l+3
            acc[0] += wq * u.x; acc[1] += wq * u.y;
            acc[2] += wq * u.z; acc[3] += wq * u.w;
        }
    }
    int b = batch[w];
#pragma unroll
    for (int j = 0; j < 4; j++) {
        int d = 4 * l + j;
        float v = acc[j] + b2[d];
        v = v > 0.f ? v : 0.f;
        atomicAdd(&g_pool[b * 128 + d], v);
    }
    if (l == 0) atomicAdd(&g_gcnt[b], 1);
}

// ---------------- classifier head -------------------------------------------
__global__ void k_class(const float* __restrict__ Wc1, const float* __restrict__ bc1,
                        const float* __restrict__ Wc2, const float* __restrict__ bc2,
                        float* __restrict__ out) {
    int g = blockIdx.x, t = threadIdx.x;
    __shared__ float p[128];
    __shared__ float z[64];
    float c = fmaxf((float)g_gcnt[g], 1.f);
    p[t] = g_pool[g * 128 + t] / c;
    __syncthreads();
    if (t < 64) {
        float s = bc1[t];
        for (int i = 0; i < 128; i++) s += p[i] * Wc1[i * 64 + t];
        z[t] = s > 0.f ? s : 0.f;
    }
    __syncthreads();
    if (t < 4) {
        float s = bc2[t];
        for (int i = 0; i < 64; i++) s += z[i] * Wc2[i * 4 + t];
        out[g * 4 + t] = s;
    }
}

// ---------------- launch -----------------------------------------------------
extern "C" void kernel_launch(void* const* d_in, const int* in_sizes, int n_in,
                              void* d_out, int out_size) {
    const float* x      = (const float*)d_in[0];
    const int*   ei     = (const int*)d_in[1];
    const int*   batch  = (const int*)d_in[2];
    const float* attn_W = (const float*)d_in[3];
    const float* attn_b = (const float*)d_in[4];
    const float* W1     = (const float*)d_in[5];
    const float* as1    = (const float*)d_in[6];
    const float* ad1    = (const float*)d_in[7];
    const float* b1     = (const float*)d_in[8];
    const float* W2     = (const float*)d_in[9];
    const float* as2    = (const float*)d_in[10];
    const float* ad2    = (const float*)d_in[11];
    const float* b2     = (const float*)d_in[12];
    const float* Wc1    = (const float*)d_in[13];
    const float* bc1    = (const float*)d_in[14];
    const float* Wc2    = (const float*)d_in[15];
    const float* bc2    = (const float*)d_in[16];
    float* out = (float*)d_out;

    float* p_h1;   cudaGetSymbolAddress((void**)&p_h1, g_h1);
    float* p_h2;   cudaGetSymbolAddress((void**)&p_h2, g_h2);
    __nv_bfloat16 *p_xh, *p_xl, *p_a1h, *p_a1l, *p_w1h, *p_w1l, *p_w2h, *p_w2l;
    cudaGetSymbolAddress((void**)&p_xh, g_xhi);
    cudaGetSymbolAddress((void**)&p_xl, g_xlo);
    cudaGetSymbolAddress((void**)&p_a1h, g_a1hi);
    cudaGetSymbolAddress((void**)&p_a1l, g_a1lo);
    cudaGetSymbolAddress((void**)&p_w1h, g_W1Thi);
    cudaGetSymbolAddress((void**)&p_w1l, g_W1Tlo);
    cudaGetSymbolAddress((void**)&p_w2h, g_W2Thi);
    cudaGetSymbolAddress((void**)&p_w2l, g_W2Tlo);

    cudaFuncSetAttribute(k_gemm_cp<KPAD1, 256>,
                         cudaFuncAttributeMaxDynamicSharedMemorySize, GSMEM_BYTES);
    cudaFuncSetAttribute(k_gemm_cp<256, 128>,
                         cudaFuncAttributeMaxDynamicSharedMemorySize, GSMEM_BYTES);

    const int MB = (NN + 127) / 128;  // 235

    k_attn<<<NN, 256>>>(x, attn_W, attn_b);
    k_split<<<(256 * KPAD1 + 255) / 256, 256>>>(W1, W2);
    k_gemm_cp<KPAD1, 256><<<dim3(2, MB), 256, GSMEM_BYTES>>>(p_xh, p_xl, p_w1h, p_w1l, p_h1);
    k_alpha1<<<(NN * 32 + 255) / 256, 256>>>(as1, ad1);
    k_count<<<(NE + 255) / 256, 256>>>(ei);
    k_scan<<<1, 1024>>>();
    k_scatter<<<(NE + 255) / 256, 256>>>(ei);
    k_agg1<<<(NN * 32 + 255) / 256, 256>>>(b1);
    k_gemm_cp<256, 128><<<dim3(1, MB), 256, GSMEM_BYTES>>>(p_a1h, p_a1l, p_w2h, p_w2l, p_h2);
    k_alpha2<<<(NN * 32 + 255) / 256, 256>>>(as2, ad2);
    k_agg2<<<(NN * 32 + 255) / 256, 256>>>(b2, batch);
    k_class<<<64, 128>>>(Wc1, bc1, Wc2, bc2, out);
}

// round 9
// speedup vs baseline: 1.1214x; 1.1214x over previous
#include <cuda_runtime.h>
#include <cuda_bf16.h>
#include <math.h>
#include <stdint.h>

#define NN    30000
#define NE    960000
#define ET    (NE + NN)
#define INDIM 4527
#define KPAD1 4544
#define HOGD  4464
#define HID   128
#define NG    64

// ---------------- scratch (device globals) ----------------------------------
__device__ float g_h1[NN * 256];
__device__ float g_as1[NN * 2];
__device__ float g_ad1[NN * 2];
__device__ float g_h2[NN * HID];
__device__ float g_as2[NN];
__device__ float g_ad2[NN];
__device__ int   g_cntN[NN];
__device__ int   g_indptr[NN + 1];
__device__ int   g_cursor[NN];
__device__ int   g_srcs[ET];
__device__ float g_pool[NG * HID];
__device__ int   g_gcnt[NG];
// pre-split bf16 operands (+128 row slack so OOB tile loads stay in-bounds)
__device__ __nv_bfloat16 g_xhi[(NN + 128) * KPAD1];
__device__ __nv_bfloat16 g_xlo[(NN + 128) * KPAD1];
__device__ __nv_bfloat16 g_a1hi[(NN + 128) * 256];
__device__ __nv_bfloat16 g_a1lo[(NN + 128) * 256];
__device__ __nv_bfloat16 g_W1Thi[256 * KPAD1];
__device__ __nv_bfloat16 g_W1Tlo[256 * KPAD1];
__device__ __nv_bfloat16 g_W2Thi[128 * 256];
__device__ __nv_bfloat16 g_W2Tlo[128 * 256];

// ---------------- helpers ---------------------------------------------------
__device__ __forceinline__ uint32_t smem_u32(const void* p) {
    uint32_t a;
    asm("{ .reg .u64 t; cvta.to.shared.u64 t, %1; cvt.u32.u64 %0, t; }"
        : "=r"(a) : "l"(p));
    return a;
}
__device__ __forceinline__ float warpSum(float v) {
#pragma unroll
    for (int o = 16; o; o >>= 1) v += __shfl_xor_sync(0xffffffffu, v, o);
    return v;
}
__device__ __forceinline__ float warpMax(float v) {
#pragma unroll
    for (int o = 16; o; o >>= 1) v = fmaxf(v, __shfl_xor_sync(0xffffffffu, v, o));
    return v;
}
__device__ __forceinline__ float lrelu(float v) { return v > 0.f ? v : 0.2f * v; }

__device__ __forceinline__ void mma16816(float c[4], const uint32_t a[4],
                                         uint32_t b0, uint32_t b1) {
    asm volatile(
        "mma.sync.aligned.m16n8k16.row.col.f32.bf16.bf16.f32 "
        "{%0,%1,%2,%3}, {%4,%5,%6,%7}, {%8,%9}, {%0,%1,%2,%3};"
        : "+f"(c[0]), "+f"(c[1]), "+f"(c[2]), "+f"(c[3])
        : "r"(a[0]), "r"(a[1]), "r"(a[2]), "r"(a[3]), "r"(b0), "r"(b1));
}
#define LDSM4(r0, r1, r2, r3, addr)                                           \
    asm volatile("ldmatrix.sync.aligned.m8n8.x4.shared.b16 {%0,%1,%2,%3}, [%4];" \
                 : "=r"(r0), "=r"(r1), "=r"(r2), "=r"(r3) : "r"(addr))
#define CP16(saddr, gaddr)                                                    \
    asm volatile("cp.async.cg.shared.global [%0], [%1], 16;"                  \
                 :: "r"(saddr), "l"(gaddr))
#define CP_COMMIT() asm volatile("cp.async.commit_group;" ::: "memory")
#define CP_WAIT1()  asm volatile("cp.async.wait_group 1;" ::: "memory")

__device__ __forceinline__ unsigned packsplit(float v0, float v1, float& r0, float& r1) {
    __nv_bfloat16 h0 = __float2bfloat16(v0), h1 = __float2bfloat16(v1);
    r0 = v0 - __bfloat162float(h0);
    r1 = v1 - __bfloat162float(h1);
    unsigned short a = *(unsigned short*)&h0, b = *(unsigned short*)&h1;
    return (unsigned)a | ((unsigned)b << 16);
}
__device__ __forceinline__ unsigned packlo(float v0, float v1) {
    __nv_bfloat16 h0 = __float2bfloat16(v0), h1 = __float2bfloat16(v1);
    unsigned short a = *(unsigned short*)&h0, b = *(unsigned short*)&h1;
    return (unsigned)a | ((unsigned)b << 16);
}

// ---------------- attention gate + split gated x (x read ONCE) --------------
__global__ __launch_bounds__(256) void k_attn(const float* __restrict__ x,
                                              const float* __restrict__ aW,
                                              const float* __restrict__ ab) {
    int n = blockIdx.x;
    int t = threadIdx.x;  // 256
    // absorbed k_init (runs strictly before k_count / agg kernels)
    {
        int i = n * 256 + t;
        if (i < NN) g_cntN[i] = 1;
        if (i < NG * HID) g_pool[i] = 0.f;
        if (i < NG) g_gcnt[i] = 0;
    }
    const float* xr = x + (size_t)n * INDIM;
    const float2* aW2 = (const float2*)aW;

    float v[5][4];   // register-cached x values (raw, pre-gate)
    float p0 = 0.f, p1 = 0.f;
#pragma unroll
    for (int i = 0; i < 5; i++) {
        int p = t + i * 256;
#pragma unroll
        for (int j = 0; j < 4; j++) {
            int k = 4 * p + j;
            float val = 0.f;
            if (k < INDIM) {
                val = xr[k];
                float2 wv = aW2[k];
                p0 += val * wv.x;
                p1 += val * wv.y;
            }
            v[i][j] = val;
        }
    }
    p0 = warpSum(p0);
    p1 = warpSum(p1);
    __shared__ float s0[8], s1[8];
    __shared__ float gg[2];
    if ((t & 31) == 0) { s0[t >> 5] = p0; s1[t >> 5] = p1; }
    __syncthreads();
    if (t == 0) {
        p0 = ab[0]; p1 = ab[1];
#pragma unroll
        for (int i = 0; i < 8; i++) { p0 += s0[i]; p1 += s1[i]; }
        float m = fmaxf(p0, p1);
        float e0 = expf(p0 - m), e1 = expf(p1 - m);
        float inv = 1.f / (e0 + e1);
        gg[0] = e0 * inv;
        gg[1] = e1 * inv;
    }
    __syncthreads();
    float g0 = gg[0], g1 = gg[1];
    uint2* oh = (uint2*)(g_xhi + (size_t)n * KPAD1);
    uint2* ol = (uint2*)(g_xlo + (size_t)n * KPAD1);
#pragma unroll
    for (int i = 0; i < 5; i++) {
        int p = t + i * 256;
        if (p < KPAD1 / 4) {
            int k = 4 * p;
            float w0 = v[i][0] * ((k     < HOGD) ? g0 : g1);
            float w1 = v[i][1] * ((k + 1 < HOGD) ? g0 : g1);
            float w2 = v[i][2] * ((k + 2 < HOGD) ? g0 : g1);
            float w3 = v[i][3] * ((k + 3 < HOGD) ? g0 : g1);
            float r0, r1, r2, r3;
            uint2 hi, lo;
            hi.x = packsplit(w0, w1, r0, r1);
            hi.y = packsplit(w2, w3, r2, r3);
            lo.x = packlo(r0, r1);
            lo.y = packlo(r2, r3);
            oh[p] = hi;
            ol[p] = lo;
        }
    }
}

// ---------------- weight split (+transpose to [n][k]) -----------------------
__global__ void k_split(const float* __restrict__ W1, const float* __restrict__ W2) {
    int i = blockIdx.x * blockDim.x + threadIdx.x;
    if (i < 256 * KPAD1) {
        int n = i / KPAD1, k = i % KPAD1;
        float v = (k < INDIM) ? W1[(size_t)k * 256 + n] : 0.f;
        __nv_bfloat16 h = __float2bfloat16(v);
        g_W1Thi[i] = h;
        g_W1Tlo[i] = __float2bfloat16(v - __bfloat162float(h));
    }
    if (i < 128 * 256) {
        int n = i / 256, k = i % 256;
        float v = W2[k * 128 + n];
        __nv_bfloat16 h = __float2bfloat16(v);
        g_W2Thi[i] = h;
        g_W2Tlo[i] = __float2bfloat16(v - __bfloat162float(h));
    }
}

// ---------------- split-bf16 tensor GEMM, 3-stage swizzled pipeline ---------
// (R6-proven mainloop: cp issued right after barrier, both ks blocks after)
#define PARTB   8192
#define STAGEB  (4 * PARTB)
#define GSMEM_BYTES (3 * STAGEB + 1024)

template <int KPADT, int NTOT>
__global__ __launch_bounds__(256, 2)
void k_gemm_cp(const __nv_bfloat16* __restrict__ Ahi,
               const __nv_bfloat16* __restrict__ Alo,
               const __nv_bfloat16* __restrict__ Bhi,
               const __nv_bfloat16* __restrict__ Blo,
               float* __restrict__ C) {
    constexpr int KT = KPADT / 32;
    extern __shared__ char smraw[];
    char* smb = (char*)(((uintptr_t)smraw + 1023) & ~(uintptr_t)1023);
    const uint32_t sb = smem_u32(smb);
    const int tid = threadIdx.x;
    const int l = tid & 31, w = tid >> 5;
    const int wm = w >> 2, wn = w & 3;       // 2x4 grid, 64x32 warp tiles
    const int bn = blockIdx.x * 128;
    const int bm = blockIdx.y * 128;

    const int crow = tid >> 1;
    const int cp0 = (tid & 1) * 2;
    const int csw = (crow >> 1) & 3;
    const uint32_t cs0 = (uint32_t)(crow * 64 + ((cp0 ^ csw) * 16));
    const uint32_t cs1 = (uint32_t)(crow * 64 + (((cp0 + 1) ^ csw) * 16));
    const __nv_bfloat16* aHiP = Ahi + (size_t)(bm + crow) * KPADT + cp0 * 8;
    const __nv_bfloat16* aLoP = Alo + (size_t)(bm + crow) * KPADT + cp0 * 8;
    const __nv_bfloat16* bHiP = Bhi + (size_t)(bn + crow) * KPADT + cp0 * 8;
    const __nv_bfloat16* bLoP = Blo + (size_t)(bn + crow) * KPADT + cp0 * 8;

    float acc[4][4][4];
#pragma unroll
    for (int i = 0; i < 4; i++)
#pragma unroll
        for (int j = 0; j < 4; j++)
#pragma unroll
            for (int q = 0; q < 4; q++) acc[i][j][q] = 0.f;

    auto cpStage = [&](int kt, int s) {
        const int k0 = kt * 32;
        uint32_t d = sb + s * STAGEB;
        CP16(d + cs0,             (const char*)(aHiP + k0));
        CP16(d + cs1,             (const char*)(aHiP + k0 + 8));
        CP16(d + PARTB + cs0,     (const char*)(aLoP + k0));
        CP16(d + PARTB + cs1,     (const char*)(aLoP + k0 + 8));
        CP16(d + 2 * PARTB + cs0, (const char*)(bHiP + k0));
        CP16(d + 2 * PARTB + cs1, (const char*)(bHiP + k0 + 8));
        CP16(d + 3 * PARTB + cs0, (const char*)(bLoP + k0));
        CP16(d + 3 * PARTB + cs1, (const char*)(bLoP + k0 + 8));
    };

    const uint32_t a_roff = (uint32_t)((wm * 64 + (l & 15)) * 64);
    const int sA = ((l & 15) >> 1) & 3;
    const int aC = (l >> 4) & 1;
    const uint32_t b_rl = (uint32_t)(((l >> 4) & 1) * 8 + (l & 7));
    const uint32_t b_roff = (uint32_t)((wn * 32) * 64) + b_rl * 64;
    const int sB = (int)((b_rl >> 1) & 3);
    const int bC = (l >> 3) & 1;

    cpStage(0, 0);
    CP_COMMIT();
    cpStage(1, 1);
    CP_COMMIT();

    int s = 0;
    for (int kt = 0; kt < KT; kt++) {
        CP_WAIT1();
        __syncthreads();
        if (kt + 2 < KT) {
            int ns = s + 2; if (ns >= 3) ns -= 3;
            cpStage(kt + 2, ns);
        }
        CP_COMMIT();

        const uint32_t stb = sb + s * STAGEB;
#pragma unroll
        for (int ks = 0; ks < 2; ks++) {
            const uint32_t ca = (uint32_t)(((2 * ks + aC) ^ sA) * 16);
            const uint32_t cb = (uint32_t)(((2 * ks + bC) ^ sB) * 16);
            uint32_t ah[4][4], al[4][4];
#pragma unroll
            for (int mt = 0; mt < 4; mt++) {
                uint32_t off = a_roff + mt * 1024 + ca;
                LDSM4(ah[mt][0], ah[mt][1], ah[mt][2], ah[mt][3], stb + off);
                LDSM4(al[mt][0], al[mt][1], al[mt][2], al[mt][3],
                      stb + PARTB + off);
            }
            uint32_t bh[4][2], bl[4][2];
#pragma unroll
            for (int pr = 0; pr < 2; pr++) {
                uint32_t off = b_roff + pr * 1024 + cb;
                LDSM4(bh[2 * pr][0], bh[2 * pr][1], bh[2 * pr + 1][0],
                      bh[2 * pr + 1][1], stb + 2 * PARTB + off);
                LDSM4(bl[2 * pr][0], bl[2 * pr][1], bl[2 * pr + 1][0],
                      bl[2 * pr + 1][1], stb + 3 * PARTB + off);
            }
#pragma unroll
            for (int nt = 0; nt < 4; nt++)
#pragma unroll
                for (int mt = 0; mt < 4; mt++) {
                    mma16816(acc[mt][nt], ah[mt], bh[nt][0], bh[nt][1]);
                    mma16816(acc[mt][nt], ah[mt], bl[nt][0], bl[nt][1]);
                    mma16816(acc[mt][nt], al[mt], bh[nt][0], bh[nt][1]);
                }
        }
        if (++s == 3) s = 0;
    }

    const int g = l >> 2, tq = l & 3;
#pragma unroll
    for (int mt = 0; mt < 4; mt++)
#pragma unroll
        for (int nt = 0; nt < 4; nt++) {
            int m0 = bm + wm * 64 + mt * 16 + g;
            int n = bn + wn * 32 + nt * 8 + 2 * tq;
            if (m0 < NN)
                *(float2*)&C[(size_t)m0 * NTOT + n] =
                    make_float2(acc[mt][nt][0], acc[mt][nt][1]);
            if (m0 + 8 < NN)
                *(float2*)&C[(size_t)(m0 + 8) * NTOT + n] =
                    make_float2(acc[mt][nt][2], acc[mt][nt][3]);
        }
}

// ---------------- alpha layer 1 (scalar col-strided — proven) ---------------
__global__ void k_alpha1(const float* __restrict__ as1,
                         const float* __restrict__ ad1) {
    int w = (blockIdx.x * blockDim.x + threadIdx.x) >> 5;
    int l = threadIdx.x & 31;
    if (w >= NN) return;
    const float* hr = g_h1 + (size_t)w * 256;
    float ps0 = 0, pd0 = 0, ps1 = 0, pd1 = 0;
#pragma unroll
    for (int i = 0; i < 4; i++) {
        int d = l + i * 32;
        float v0 = hr[d], v1 = hr[128 + d];
        ps0 += v0 * as1[d];        pd0 += v0 * ad1[d];
        ps1 += v1 * as1[128 + d];  pd1 += v1 * ad1[128 + d];
    }
    ps0 = warpSum(ps0); pd0 = warpSum(pd0);
    ps1 = warpSum(ps1); pd1 = warpSum(pd1);
    if (l == 0) {
        g_as1[2 * w] = ps0; g_as1[2 * w + 1] = ps1;
        g_ad1[2 * w] = pd0; g_ad1[2 * w + 1] = pd1;
    }
}

// ---------------- CSR build --------------------------------------------------
__global__ void k_count(const int* __restrict__ ei) {
    int e = blockIdx.x * blockDim.x + threadIdx.x;
    if (e < NE) atomicAdd(&g_cntN[ei[NE + e]], 1);
}

__global__ void k_scan() {
    __shared__ int sh[1024];
    int t = threadIdx.x;
    const int CH = (NN + 1023) / 1024;
    int lo = t * CH, hi = min(lo + CH, NN);
    int s = 0;
    for (int i = lo; i < hi; i++) s += g_cntN[i];
    sh[t] = s;
    __syncthreads();
    for (int o = 1; o < 1024; o <<= 1) {
        int v = (t >= o) ? sh[t - o] : 0;
        __syncthreads();
        sh[t] += v;
        __syncthreads();
    }
    int run = (t == 0) ? 0 : sh[t - 1];
    for (int i = lo; i < hi; i++) {
        g_indptr[i] = run;
        g_srcs[run] = i;      // self loop first in bucket
        g_cursor[i] = 1;
        run += g_cntN[i];
    }
    if (t == 1023) g_indptr[NN] = sh[1023];
}

__global__ void k_scatter(const int* __restrict__ ei) {
    int e = blockIdx.x * blockDim.x + threadIdx.x;
    if (e < NE) {
        int s = ei[e], d = ei[NE + e];
        int pos = g_indptr[d] + atomicAdd(&g_cursor[d], 1);
        g_srcs[pos] = s;
    }
}

// ---------------- layer-1 aggregation (scalar gather — proven) --------------
__global__ void k_agg1(const float* __restrict__ b1) {
    int w = (blockIdx.x * blockDim.x + threadIdx.x) >> 5;
    int l = threadIdx.x & 31;
    if (w >= NN) return;
    int beg = g_indptr[w], end = g_indptr[w + 1];
    float ad0 = g_ad1[2 * w], ad1 = g_ad1[2 * w + 1];

    float m0 = -1e30f, m1 = -1e30f;
    for (int j = beg + l; j < end; j += 32) {
        int s = g_srcs[j];
        m0 = fmaxf(m0, lrelu(g_as1[2 * s] + ad0));
        m1 = fmaxf(m1, lrelu(g_as1[2 * s + 1] + ad1));
    }
    m0 = warpMax(m0); m1 = warpMax(m1);

    float d0 = 0.f, d1 = 0.f;
    for (int j = beg + l; j < end; j += 32) {
        int s = g_srcs[j];
        d0 += expf(lrelu(g_as1[2 * s] + ad0) - m0);
        d1 += expf(lrelu(g_as1[2 * s + 1] + ad1) - m1);
    }
    d0 = warpSum(d0); d1 = warpSum(d1);
    float i0 = 1.f / (d0 + 1e-16f), i1 = 1.f / (d1 + 1e-16f);

    float acc[8] = {0, 0, 0, 0, 0, 0, 0, 0};
    for (int base = beg; base < end; base += 32) {
        int j = base + l;
        int s = 0; float w0 = 0.f, w1 = 0.f;
        if (j < end) {
            s = g_srcs[j];
            w0 = expf(lrelu(g_as1[2 * s] + ad0) - m0) * i0;
            w1 = expf(lrelu(g_as1[2 * s + 1] + ad1) - m1) * i1;
        }
        int cnt = min(32, end - base);
        for (int q = 0; q < cnt; q++) {
            int   sq  = __shfl_sync(0xffffffffu, s, q);
            float w0q = __shfl_sync(0xffffffffu, w0, q);
            float w1q = __shfl_sync(0xffffffffu, w1, q);
            const float* hp = g_h1 + (size_t)sq * 256 + l;
            acc[0] += w0q * hp[0];   acc[1] += w0q * hp[32];
            acc[2] += w0q * hp[64];  acc[3] += w0q * hp[96];
            acc[4] += w1q * hp[128]; acc[5] += w1q * hp[160];
            acc[6] += w1q * hp[192]; acc[7] += w1q * hp[224];
        }
    }
#pragma unroll
    for (int i = 0; i < 8; i++) {
        int d = l + i * 32;
        float v = acc[i] + b1[d];
        v = v > 0.f ? v : 0.f;
        __nv_bfloat16 h = __float2bfloat16(v);
        g_a1hi[(size_t)w * 256 + d] = h;
        g_a1lo[(size_t)w * 256 + d] = __float2bfloat16(v - __bfloat162float(h));
    }
}

// ---------------- alpha layer 2 (scalar — proven) ----------------------------
__global__ void k_alpha2(const float* __restrict__ as2,
                         const float* __restrict__ ad2) {
    int w = (blockIdx.x * blockDim.x + threadIdx.x) >> 5;
    int l = threadIdx.x & 31;
    if (w >= NN) return;
    const float* hr = g_h2 + (size_t)w * 128;
    float ps = 0.f, pd = 0.f;
#pragma unroll
    for (int i = 0; i < 4; i++) {
        int d = l + i * 32;
        float v = hr[d];
        ps += v * as2[d];
        pd += v * ad2[d];
    }
    ps = warpSum(ps); pd = warpSum(pd);
    if (l == 0) { g_as2[w] = ps; g_ad2[w] = pd; }
}

// ---------------- layer-2 aggregation + pooling (scalar — proven) -----------
__global__ void k_agg2(const float* __restrict__ b2,
                       const int* __restrict__ batch) {
    int w = (blockIdx.x * blockDim.x + threadIdx.x) >> 5;
    int l = threadIdx.x & 31;
    if (w >= NN) return;
    int beg = g_indptr[w], end = g_indptr[w + 1];
    float ad = g_ad2[w];

    float m = -1e30f;
    for (int j = beg + l; j < end; j += 32)
        m = fmaxf(m, lrelu(g_as2[g_srcs[j]] + ad));
    m = warpMax(m);

    float den = 0.f;
    for (int j = beg + l; j < end; j += 32)
        den += expf(lrelu(g_as2[g_srcs[j]] + ad) - m);
    den = warpSum(den);
    float inv = 1.f / (den + 1e-16f);

    float acc[4] = {0, 0, 0, 0};
    for (int base = beg; base < end; base += 32) {
        int j = base + l;
        int s = 0; float ww = 0.f;
        if (j < end) {
            s = g_srcs[j];
            ww = expf(lrelu(g_as2[s] + ad) - m) * inv;
        }
        int cnt = min(32, end - base);
        for (int q = 0; q < cnt; q++) {
            int   sq = __shfl_sync(0xffffffffu, s, q);
            float wq = __shfl_sync(0xffffffffu, ww, q);
            const float* hp = g_h2 + (size_t)sq * 128 + l;
            acc[0] += wq * hp[0];  acc[1] += wq * hp[32];
            acc[2] += wq * hp[64]; acc[3] += wq * hp[96];
        }
    }
    int b = batch[w];
#pragma unroll
    for (int i = 0; i < 4; i++) {
        int d = l + i * 32;
        float v = acc[i] + b2[d];
        v = v > 0.f ? v : 0.f;
        atomicAdd(&g_pool[b * 128 + d], v);
    }
    if (l == 0) atomicAdd(&g_gcnt[b], 1);
}

// ---------------- classifier head -------------------------------------------
__global__ void k_class(const float* __restrict__ Wc1, const float* __restrict__ bc1,
                        const float* __restrict__ Wc2, const float* __restrict__ bc2,
                        float* __restrict__ out) {
    int g = blockIdx.x, t = threadIdx.x;
    __shared__ float p[128];
    __shared__ float z[64];
    float c = fmaxf((float)g_gcnt[g], 1.f);
    p[t] = g_pool[g * 128 + t] / c;
    __syncthreads();
    if (t < 64) {
        float s = bc1[t];
        for (int i = 0; i < 128; i++) s += p[i] * Wc1[i * 64 + t];
        z[t] = s > 0.f ? s : 0.f;
    }
    __syncthreads();
    if (t < 4) {
        float s = bc2[t];
        for (int i = 0; i < 64; i++) s += z[i] * Wc2[i * 4 + t];
        out[g * 4 + t] = s;
    }
}

// ---------------- launch -----------------------------------------------------
extern "C" void kernel_launch(void* const* d_in, const int* in_sizes, int n_in,
                              void* d_out, int out_size) {
    const float* x      = (const float*)d_in[0];
    const int*   ei     = (const int*)d_in[1];
    const int*   batch  = (const int*)d_in[2];
    const float* attn_W = (const float*)d_in[3];
    const float* attn_b = (const float*)d_in[4];
    const float* W1     = (const float*)d_in[5];
    const float* as1    = (const float*)d_in[6];
    const float* ad1    = (const float*)d_in[7];
    const float* b1     = (const float*)d_in[8];
    const float* W2     = (const float*)d_in[9];
    const float* as2    = (const float*)d_in[10];
    const float* ad2    = (const float*)d_in[11];
    const float* b2     = (const float*)d_in[12];
    const float* Wc1    = (const float*)d_in[13];
    const float* bc1    = (const float*)d_in[14];
    const float* Wc2    = (const float*)d_in[15];
    const float* bc2    = (const float*)d_in[16];
    float* out = (float*)d_out;

    float* p_h1;   cudaGetSymbolAddress((void**)&p_h1, g_h1);
    float* p_h2;   cudaGetSymbolAddress((void**)&p_h2, g_h2);
    __nv_bfloat16 *p_xh, *p_xl, *p_a1h, *p_a1l, *p_w1h, *p_w1l, *p_w2h, *p_w2l;
    cudaGetSymbolAddress((void**)&p_xh, g_xhi);
    cudaGetSymbolAddress((void**)&p_xl, g_xlo);
    cudaGetSymbolAddress((void**)&p_a1h, g_a1hi);
    cudaGetSymbolAddress((void**)&p_a1l, g_a1lo);
    cudaGetSymbolAddress((void**)&p_w1h, g_W1Thi);
    cudaGetSymbolAddress((void**)&p_w1l, g_W1Tlo);
    cudaGetSymbolAddress((void**)&p_w2h, g_W2Thi);
    cudaGetSymbolAddress((void**)&p_w2l, g_W2Tlo);

    cudaFuncSetAttribute(k_gemm_cp<KPAD1, 256>,
                         cudaFuncAttributeMaxDynamicSharedMemorySize, GSMEM_BYTES);
    cudaFuncSetAttribute(k_gemm_cp<256, 128>,
                         cudaFuncAttributeMaxDynamicSharedMemorySize, GSMEM_BYTES);

    const int MB = (NN + 127) / 128;  // 235

    k_attn<<<NN, 256>>>(x, attn_W, attn_b);
    k_split<<<(256 * KPAD1 + 255) / 256, 256>>>(W1, W2);
    k_gemm_cp<KPAD1, 256><<<dim3(2, MB), 256, GSMEM_BYTES>>>(p_xh, p_xl, p_w1h, p_w1l, p_h1);
    k_alpha1<<<(NN * 32 + 255) / 256, 256>>>(as1, ad1);
    k_count<<<(NE + 255) / 256, 256>>>(ei);
    k_scan<<<1, 1024>>>();
    k_scatter<<<(NE + 255) / 256, 256>>>(ei);
    k_agg1<<<(NN * 32 + 255) / 256, 256>>>(b1);
    k_gemm_cp<256, 128><<<dim3(1, MB), 256, GSMEM_BYTES>>>(p_a1h, p_a1l, p_w2h, p_w2l, p_h2);
    k_alpha2<<<(NN * 32 + 255) / 256, 256>>>(as2, ad2);
    k_agg2<<<(NN * 32 + 255) / 256, 256>>>(b2, batch);
    k_class<<<64, 128>>>(Wc1, bc1, Wc2, bc2, out);
}

// round 11
// speedup vs baseline: 1.1304x; 1.0081x over previous
#include <cuda_runtime.h>
#include <cuda_bf16.h>
#include <math.h>
#include <stdint.h>

#define NN    30000
#define NE    960000
#define ET    (NE + NN)
#define INDIM 4527
#define KPAD1 4544
#define HOGD  4464
#define HID   128
#define NG    64

// ---------------- scratch (device globals) ----------------------------------
__device__ float g_h1[NN * 256];
__device__ float g_as1[NN * 2];
__device__ float g_ad1[NN * 2];
__device__ float g_h2[NN * HID];
__device__ float g_as2[NN];
__device__ float g_ad2[NN];
__device__ int   g_cntN[NN];
__device__ int   g_indptr[NN + 1];
__device__ int   g_cursor[NN];
__device__ int   g_srcs[ET];
__device__ float g_pool[NG * HID];
__device__ int   g_gcnt[NG];
// pre-split bf16 operands (+128 row slack so OOB tile loads stay in-bounds)
__device__ __nv_bfloat16 g_xhi[(NN + 128) * KPAD1];
__device__ __nv_bfloat16 g_xlo[(NN + 128) * KPAD1];
__device__ __nv_bfloat16 g_a1hi[(NN + 128) * 256];
__device__ __nv_bfloat16 g_a1lo[(NN + 128) * 256];
__device__ __nv_bfloat16 g_W1Thi[256 * KPAD1];
__device__ __nv_bfloat16 g_W1Tlo[256 * KPAD1];
__device__ __nv_bfloat16 g_W2Thi[128 * 256];
__device__ __nv_bfloat16 g_W2Tlo[128 * 256];

// ---------------- helpers ---------------------------------------------------
__device__ __forceinline__ uint32_t smem_u32(const void* p) {
    uint32_t a;
    asm("{ .reg .u64 t; cvta.to.shared.u64 t, %1; cvt.u32.u64 %0, t; }"
        : "=r"(a) : "l"(p));
    return a;
}
__device__ __forceinline__ float warpSum(float v) {
#pragma unroll
    for (int o = 16; o; o >>= 1) v += __shfl_xor_sync(0xffffffffu, v, o);
    return v;
}
__device__ __forceinline__ float warpMax(float v) {
#pragma unroll
    for (int o = 16; o; o >>= 1) v = fmaxf(v, __shfl_xor_sync(0xffffffffu, v, o));
    return v;
}
__device__ __forceinline__ float lrelu(float v) { return v > 0.f ? v : 0.2f * v; }

__device__ __forceinline__ void mma16816(float c[4], const uint32_t a[4],
                                         uint32_t b0, uint32_t b1) {
    asm volatile(
        "mma.sync.aligned.m16n8k16.row.col.f32.bf16.bf16.f32 "
        "{%0,%1,%2,%3}, {%4,%5,%6,%7}, {%8,%9}, {%0,%1,%2,%3};"
        : "+f"(c[0]), "+f"(c[1]), "+f"(c[2]), "+f"(c[3])
        : "r"(a[0]), "r"(a[1]), "r"(a[2]), "r"(a[3]), "r"(b0), "r"(b1));
}
#define LDSM4(r0, r1, r2, r3, addr)                                           \
    asm volatile("ldmatrix.sync.aligned.m8n8.x4.shared.b16 {%0,%1,%2,%3}, [%4];" \
                 : "=r"(r0), "=r"(r1), "=r"(r2), "=r"(r3) : "r"(addr))
#define CP16(saddr, gaddr)                                                    \
    asm volatile("cp.async.cg.shared.global [%0], [%1], 16;"                  \
                 :: "r"(saddr), "l"(gaddr))
#define CP_COMMIT() asm volatile("cp.async.commit_group;" ::: "memory")
#define CP_WAIT1()  asm volatile("cp.async.wait_group 1;" ::: "memory")

__device__ __forceinline__ unsigned packsplit(float v0, float v1, float& r0, float& r1) {
    __nv_bfloat16 h0 = __float2bfloat16(v0), h1 = __float2bfloat16(v1);
    r0 = v0 - __bfloat162float(h0);
    r1 = v1 - __bfloat162float(h1);
    unsigned short a = *(unsigned short*)&h0, b = *(unsigned short*)&h1;
    return (unsigned)a | ((unsigned)b << 16);
}
__device__ __forceinline__ unsigned packlo(float v0, float v1) {
    __nv_bfloat16 h0 = __float2bfloat16(v0), h1 = __float2bfloat16(v1);
    unsigned short a = *(unsigned short*)&h0, b = *(unsigned short*)&h1;
    return (unsigned)a | ((unsigned)b << 16);
}

// ---------------- init -------------------------------------------------------
__global__ void k_init() {
    int i = blockIdx.x * blockDim.x + threadIdx.x;
    if (i < NN) g_cntN[i] = 1;
    if (i < NG * HID) g_pool[i] = 0.f;
    if (i < NG) g_gcnt[i] = 0;
}

// ---------------- attention gate + split gated x ----------------------------
__global__ void k_attn(const float* __restrict__ x,
                       const float* __restrict__ aW,
                       const float* __restrict__ ab) {
    int n = blockIdx.x;
    int t = threadIdx.x;  // 128
    const float* xr = x + (size_t)n * INDIM;
    float p0 = 0.f, p1 = 0.f;
    for (int k = t; k < INDIM; k += 128) {
        float v = xr[k];
        p0 += v * aW[2 * k];
        p1 += v * aW[2 * k + 1];
    }
    p0 = warpSum(p0);
    p1 = warpSum(p1);
    __shared__ float s0[4], s1[4];
    __shared__ float gg[2];
    if ((t & 31) == 0) { s0[t >> 5] = p0; s1[t >> 5] = p1; }
    __syncthreads();
    if (t == 0) {
        p0 = s0[0] + s0[1] + s0[2] + s0[3] + ab[0];
        p1 = s1[0] + s1[1] + s1[2] + s1[3] + ab[1];
        float m = fmaxf(p0, p1);
        float e0 = expf(p0 - m), e1 = expf(p1 - m);
        float inv = 1.f / (e0 + e1);
        gg[0] = e0 * inv;
        gg[1] = e1 * inv;
    }
    __syncthreads();
    float g0 = gg[0], g1 = gg[1];
    uint32_t* oh = (uint32_t*)(g_xhi + (size_t)n * KPAD1);
    uint32_t* ol = (uint32_t*)(g_xlo + (size_t)n * KPAD1);
    for (int p = t; p < KPAD1 / 2; p += 128) {
        int k = 2 * p;
        float v0 = 0.f, v1 = 0.f;
        if (k < INDIM)     v0 = xr[k] * ((k < HOGD) ? g0 : g1);
        if (k + 1 < INDIM) v1 = xr[k + 1] * ((k + 1 < HOGD) ? g0 : g1);
        float r0, r1;
        oh[p] = packsplit(v0, v1, r0, r1);
        ol[p] = packlo(r0, r1);
    }
}

// ---------------- weight split (+transpose to [n][k]) -----------------------
__global__ void k_split(const float* __restrict__ W1, const float* __restrict__ W2) {
    int i = blockIdx.x * blockDim.x + threadIdx.x;
    if (i < 256 * KPAD1) {
        int n = i / KPAD1, k = i % KPAD1;
        float v = (k < INDIM) ? W1[(size_t)k * 256 + n] : 0.f;
        __nv_bfloat16 h = __float2bfloat16(v);
        g_W1Thi[i] = h;
        g_W1Tlo[i] = __float2bfloat16(v - __bfloat162float(h));
    }
    if (i < 128 * 256) {
        int n = i / 256, k = i % 256;
        float v = W2[k * 128 + n];
        __nv_bfloat16 h = __float2bfloat16(v);
        g_W2Thi[i] = h;
        g_W2Tlo[i] = __float2bfloat16(v - __bfloat162float(h));
    }
}

// ---------------- split-bf16 tensor GEMM, 3-stage swizzled pipeline ---------
// 256 threads, block 128x128, BK=32, warp tile 64x32 (2x4 warp grid).
// MMA issue order: split-term OUTER -> 16 independent accumulators between
// successive writes to the same acc (no RAW stalls on HMMA latency).
#define PARTB   8192
#define STAGEB  (4 * PARTB)
#define GSMEM_BYTES (3 * STAGEB + 1024)

template <int KPADT, int NTOT>
__global__ __launch_bounds__(256, 2)
void k_gemm_cp(const __nv_bfloat16* __restrict__ Ahi,
               const __nv_bfloat16* __restrict__ Alo,
               const __nv_bfloat16* __restrict__ Bhi,
               const __nv_bfloat16* __restrict__ Blo,
               float* __restrict__ C) {
    constexpr int KT = KPADT / 32;
    extern __shared__ char smraw[];
    char* smb = (char*)(((uintptr_t)smraw + 1023) & ~(uintptr_t)1023);
    const uint32_t sb = smem_u32(smb);
    const int tid = threadIdx.x;
    const int l = tid & 31, w = tid >> 5;
    const int wm = w >> 2, wn = w & 3;       // 2x4 grid, 64x32 warp tiles
    const int bn = blockIdx.x * 128;
    const int bm = blockIdx.y * 128;

    const int crow = tid >> 1;
    const int cp0 = (tid & 1) * 2;
    const int csw = (crow >> 1) & 3;
    const uint32_t cs0 = (uint32_t)(crow * 64 + ((cp0 ^ csw) * 16));
    const uint32_t cs1 = (uint32_t)(crow * 64 + (((cp0 + 1) ^ csw) * 16));
    const __nv_bfloat16* aHiP = Ahi + (size_t)(bm + crow) * KPADT + cp0 * 8;
    const __nv_bfloat16* aLoP = Alo + (size_t)(bm + crow) * KPADT + cp0 * 8;
    const __nv_bfloat16* bHiP = Bhi + (size_t)(bn + crow) * KPADT + cp0 * 8;
    const __nv_bfloat16* bLoP = Blo + (size_t)(bn + crow) * KPADT + cp0 * 8;

    float acc[4][4][4];
#pragma unroll
    for (int i = 0; i < 4; i++)
#pragma unroll
        for (int j = 0; j < 4; j++)
#pragma unroll
            for (int q = 0; q < 4; q++) acc[i][j][q] = 0.f;

    auto cpStage = [&](int kt, int s) {
        const int k0 = kt * 32;
        uint32_t d = sb + s * STAGEB;
        CP16(d + cs0,             (const char*)(aHiP + k0));
        CP16(d + cs1,             (const char*)(aHiP + k0 + 8));
        CP16(d + PARTB + cs0,     (const char*)(aLoP + k0));
        CP16(d + PARTB + cs1,     (const char*)(aLoP + k0 + 8));
        CP16(d + 2 * PARTB + cs0, (const char*)(bHiP + k0));
        CP16(d + 2 * PARTB + cs1, (const char*)(bHiP + k0 + 8));
        CP16(d + 3 * PARTB + cs0, (const char*)(bLoP + k0));
        CP16(d + 3 * PARTB + cs1, (const char*)(bLoP + k0 + 8));
    };

    const uint32_t a_roff = (uint32_t)((wm * 64 + (l & 15)) * 64);
    const int sA = ((l & 15) >> 1) & 3;
    const int aC = (l >> 4) & 1;
    const uint32_t b_rl = (uint32_t)(((l >> 4) & 1) * 8 + (l & 7));
    const uint32_t b_roff = (uint32_t)((wn * 32) * 64) + b_rl * 64;
    const int sB = (int)((b_rl >> 1) & 3);
    const int bC = (l >> 3) & 1;

    cpStage(0, 0);
    CP_COMMIT();
    cpStage(1, 1);
    CP_COMMIT();

    int s = 0;
    for (int kt = 0; kt < KT; kt++) {
        CP_WAIT1();
        __syncthreads();
        if (kt + 2 < KT) {
            int ns = s + 2; if (ns >= 3) ns -= 3;
            cpStage(kt + 2, ns);
        }
        CP_COMMIT();

        const uint32_t stb = sb + s * STAGEB;
#pragma unroll
        for (int ks = 0; ks < 2; ks++) {
            const uint32_t ca = (uint32_t)(((2 * ks + aC) ^ sA) * 16);
            const uint32_t cb = (uint32_t)(((2 * ks + bC) ^ sB) * 16);
            uint32_t ah[4][4], al[4][4];
#pragma unroll
            for (int mt = 0; mt < 4; mt++) {
                uint32_t off = a_roff + mt * 1024 + ca;
                LDSM4(ah[mt][0], ah[mt][1], ah[mt][2], ah[mt][3], stb + off);
                LDSM4(al[mt][0], al[mt][1], al[mt][2], al[mt][3],
                      stb + PARTB + off);
            }
            uint32_t bh[4][2], bl[4][2];
#pragma unroll
            for (int pr = 0; pr < 2; pr++) {
                uint32_t off = b_roff + pr * 1024 + cb;
                LDSM4(bh[2 * pr][0], bh[2 * pr][1], bh[2 * pr + 1][0],
                      bh[2 * pr + 1][1], stb + 2 * PARTB + off);
                LDSM4(bl[2 * pr][0], bl[2 * pr][1], bl[2 * pr + 1][0],
                      bl[2 * pr + 1][1], stb + 3 * PARTB + off);
            }
            // term-outer issue order: 16 independent MMAs between acc reuses
#pragma unroll
            for (int nt = 0; nt < 4; nt++)
#pragma unroll
                for (int mt = 0; mt < 4; mt++)
                    mma16816(acc[mt][nt], ah[mt], bh[nt][0], bh[nt][1]);
#pragma unroll
            for (int nt = 0; nt < 4; nt++)
#pragma unroll
                for (int mt = 0; mt < 4; mt++)
                    mma16816(acc[mt][nt], ah[mt], bl[nt][0], bl[nt][1]);
#pragma unroll
            for (int nt = 0; nt < 4; nt++)
#pragma unroll
                for (int mt = 0; mt < 4; mt++)
                    mma16816(acc[mt][nt], al[mt], bh[nt][0], bh[nt][1]);
        }
        if (++s == 3) s = 0;
    }

    const int g = l >> 2, tq = l & 3;
#pragma unroll
    for (int mt = 0; mt < 4; mt++)
#pragma unroll
        for (int nt = 0; nt < 4; nt++) {
            int m0 = bm + wm * 64 + mt * 16 + g;
            int n = bn + wn * 32 + nt * 8 + 2 * tq;
            if (m0 < NN)
                *(float2*)&C[(size_t)m0 * NTOT + n] =
                    make_float2(acc[mt][nt][0], acc[mt][nt][1]);
            if (m0 + 8 < NN)
                *(float2*)&C[(size_t)(m0 + 8) * NTOT + n] =
                    make_float2(acc[mt][nt][2], acc[mt][nt][3]);
        }
}

// ---------------- alpha layer 1 ---------------------------------------------
__global__ void k_alpha1(const float* __restrict__ as1,
                         const float* __restrict__ ad1) {
    int w = (blockIdx.x * blockDim.x + threadIdx.x) >> 5;
    int l = threadIdx.x & 31;
    if (w >= NN) return;
    const float* hr = g_h1 + (size_t)w * 256;
    float ps0 = 0, pd0 = 0, ps1 = 0, pd1 = 0;
#pragma unroll
    for (int i = 0; i < 4; i++) {
        int d = l + i * 32;
        float v0 = hr[d], v1 = hr[128 + d];
        ps0 += v0 * as1[d];        pd0 += v0 * ad1[d];
        ps1 += v1 * as1[128 + d];  pd1 += v1 * ad1[128 + d];
    }
    ps0 = warpSum(ps0); pd0 = warpSum(pd0);
    ps1 = warpSum(ps1); pd1 = warpSum(pd1);
    if (l == 0) {
        g_as1[2 * w] = ps0; g_as1[2 * w + 1] = ps1;
        g_ad1[2 * w] = pd0; g_ad1[2 * w + 1] = pd1;
    }
}

// ---------------- CSR build --------------------------------------------------
__global__ void k_count(const int* __restrict__ ei) {
    int e = blockIdx.x * blockDim.x + threadIdx.x;
    if (e < NE) atomicAdd(&g_cntN[ei[NE + e]], 1);
}

__global__ void k_scan() {
    __shared__ int sh[1024];
    int t = threadIdx.x;
    const int CH = (NN + 1023) / 1024;
    int lo = t * CH, hi = min(lo + CH, NN);
    int s = 0;
    for (int i = lo; i < hi; i++) s += g_cntN[i];
    sh[t] = s;
    __syncthreads();
    for (int o = 1; o < 1024; o <<= 1) {
        int v = (t >= o) ? sh[t - o] : 0;
        __syncthreads();
        sh[t] += v;
        __syncthreads();
    }
    int run = (t == 0) ? 0 : sh[t - 1];
    for (int i = lo; i < hi; i++) { g_indptr[i] = run; run += g_cntN[i]; }
    if (t == 1023) g_indptr[NN] = sh[1023];
}

__global__ void k_self() {
    int i = blockIdx.x * blockDim.x + threadIdx.x;
    if (i < NN) { g_cursor[i] = 1; g_srcs[g_indptr[i]] = i; }
}

__global__ void k_scatter(const int* __restrict__ ei) {
    int e = blockIdx.x * blockDim.x + threadIdx.x;
    if (e < NE) {
        int s = ei[e], d = ei[NE + e];
        int pos = g_indptr[d] + atomicAdd(&g_cursor[d], 1);
        g_srcs[pos] = s;
    }
}

// ---------------- layer-1 aggregation (emits split bf16) --------------------
__global__ void k_agg1(const float* __restrict__ b1) {
    int w = (blockIdx.x * blockDim.x + threadIdx.x) >> 5;
    int l = threadIdx.x & 31;
    if (w >= NN) return;
    int beg = g_indptr[w], end = g_indptr[w + 1];
    float ad0 = g_ad1[2 * w], ad1 = g_ad1[2 * w + 1];

    float m0 = -1e30f, m1 = -1e30f;
    for (int j = beg + l; j < end; j += 32) {
        int s = g_srcs[j];
        m0 = fmaxf(m0, lrelu(g_as1[2 * s] + ad0));
        m1 = fmaxf(m1, lrelu(g_as1[2 * s + 1] + ad1));
    }
    m0 = warpMax(m0); m1 = warpMax(m1);

    float d0 = 0.f, d1 = 0.f;
    for (int j = beg + l; j < end; j += 32) {
        int s = g_srcs[j];
        d0 += expf(lrelu(g_as1[2 * s] + ad0) - m0);
        d1 += expf(lrelu(g_as1[2 * s + 1] + ad1) - m1);
    }
    d0 = warpSum(d0); d1 = warpSum(d1);
    float i0 = 1.f / (d0 + 1e-16f), i1 = 1.f / (d1 + 1e-16f);

    float acc[8] = {0, 0, 0, 0, 0, 0, 0, 0};
    for (int base = beg; base < end; base += 32) {
        int j = base + l;
        int s = 0; float w0 = 0.f, w1 = 0.f;
        if (j < end) {
            s = g_srcs[j];
            w0 = expf(lrelu(g_as1[2 * s] + ad0) - m0) * i0;
            w1 = expf(lrelu(g_as1[2 * s + 1] + ad1) - m1) * i1;
        }
        int cnt = min(32, end - base);
        for (int q = 0; q < cnt; q++) {
            int   sq  = __shfl_sync(0xffffffffu, s, q);
            float w0q = __shfl_sync(0xffffffffu, w0, q);
            float w1q = __shfl_sync(0xffffffffu, w1, q);
            const float* hp = g_h1 + (size_t)sq * 256 + l;
            acc[0] += w0q * hp[0];   acc[1] += w0q * hp[32];
            acc[2] += w0q * hp[64];  acc[3] += w0q * hp[96];
            acc[4] += w1q * hp[128]; acc[5] += w1q * hp[160];
            acc[6] += w1q * hp[192]; acc[7] += w1q * hp[224];
        }
    }
#pragma unroll
    for (int i = 0; i < 8; i++) {
        int d = l + i * 32;
        float v = acc[i] + b1[d];
        v = v > 0.f ? v : 0.f;
        __nv_bfloat16 h = __float2bfloat16(v);
        g_a1hi[(size_t)w * 256 + d] = h;
        g_a1lo[(size_t)w * 256 + d] = __float2bfloat16(v - __bfloat162float(h));
    }
}

// ---------------- alpha layer 2 ---------------------------------------------
__global__ void k_alpha2(const float* __restrict__ as2,
                         const float* __restrict__ ad2) {
    int w = (blockIdx.x * blockDim.x + threadIdx.x) >> 5;
    int l = threadIdx.x & 31;
    if (w >= NN) return;
    const float* hr = g_h2 + (size_t)w * 128;
    float ps = 0.f, pd = 0.f;
#pragma unroll
    for (int i = 0; i < 4; i++) {
        int d = l + i * 32;
        float v = hr[d];
        ps += v * as2[d];
        pd += v * ad2[d];
    }
    ps = warpSum(ps); pd = warpSum(pd);
    if (l == 0) { g_as2[w] = ps; g_ad2[w] = pd; }
}

// ---------------- layer-2 aggregation + pooling ------------------------------
__global__ void k_agg2(const float* __restrict__ b2,
                       const int* __restrict__ batch) {
    int w = (blockIdx.x * blockDim.x + threadIdx.x) >> 5;
    int l = threadIdx.x & 31;
    if (w >= NN) return;
    int beg = g_indptr[w], end = g_indptr[w + 1];
    float ad = g_ad2[w];

    float m = -1e30f;
    for (int j = beg + l; j < end; j += 32)
        m = fmaxf(m, lrelu(g_as2[g_srcs[j]] + ad));
    m = warpMax(m);

    float den = 0.f;
    for (int j = beg + l; j < end; j += 32)
        den += expf(lrelu(g_as2[g_srcs[j]] + ad) - m);
    den = warpSum(den);
    float inv = 1.f / (den + 1e-16f);

    float acc[4] = {0, 0, 0, 0};
    for (int base = beg; base < end; base += 32) {
        int j = base + l;
        int s = 0; float ww = 0.f;
        if (j < end) {
            s = g_srcs[j];
            ww = expf(lrelu(g_as2[s] + ad) - m) * inv;
        }
        int cnt = min(32, end - base);
        for (int q = 0; q < cnt; q++) {
            int   sq = __shfl_sync(0xffffffffu, s, q);
            float wq = __shfl_sync(0xffffffffu, ww, q);
            const float* hp = g_h2 + (size_t)sq * 128 + l;
            acc[0] += wq * hp[0];  acc[1] += wq * hp[32];
            acc[2] += wq * hp[64]; acc[3] += wq * hp[96];
        }
    }
    int b = batch[w];
#pragma unroll
    for (int i = 0; i < 4; i++) {
        int d = l + i * 32;
        float v = acc[i] + b2[d];
        v = v > 0.f ? v : 0.f;
        atomicAdd(&g_pool[b * 128 + d], v);
    }
    if (l == 0) atomicAdd(&g_gcnt[b], 1);
}

// ---------------- classifier head -------------------------------------------
__global__ void k_class(const float* __restrict__ Wc1, const float* __restrict__ bc1,
                        const float* __restrict__ Wc2, const float* __restrict__ bc2,
                        float* __restrict__ out) {
    int g = blockIdx.x, t = threadIdx.x;
    __shared__ float p[128];
    __shared__ float z[64];
    float c = fmaxf((float)g_gcnt[g], 1.f);
    p[t] = g_pool[g * 128 + t] / c;
    __syncthreads();
    if (t < 64) {
        float s = bc1[t];
        for (int i = 0; i < 128; i++) s += p[i] * Wc1[i * 64 + t];
        z[t] = s > 0.f ? s : 0.f;
    }
    __syncthreads();
    if (t < 4) {
        float s = bc2[t];
        for (int i = 0; i < 64; i++) s += z[i] * Wc2[i * 4 + t];
        out[g * 4 + t] = s;
    }
}

// ---------------- launch -----------------------------------------------------
extern "C" void kernel_launch(void* const* d_in, const int* in_sizes, int n_in,
                              void* d_out, int out_size) {
    const float* x      = (const float*)d_in[0];
    const int*   ei     = (const int*)d_in[1];
    const int*   batch  = (const int*)d_in[2];
    const float* attn_W = (const float*)d_in[3];
    const float* attn_b = (const float*)d_in[4];
    const float* W1     = (const float*)d_in[5];
    const float* as1    = (const float*)d_in[6];
    const float* ad1    = (const float*)d_in[7];
    const float* b1     = (const float*)d_in[8];
    const float* W2     = (const float*)d_in[9];
    const float* as2    = (const float*)d_in[10];
    const float* ad2    = (const float*)d_in[11];
    const float* b2     = (const float*)d_in[12];
    const float* Wc1    = (const float*)d_in[13];
    const float* bc1    = (const float*)d_in[14];
    const float* Wc2    = (const float*)d_in[15];
    const float* bc2    = (const float*)d_in[16];
    float* out = (float*)d_out;

    float* p_h1;   cudaGetSymbolAddress((void**)&p_h1, g_h1);
    float* p_h2;   cudaGetSymbolAddress((void**)&p_h2, g_h2);
    __nv_bfloat16 *p_xh, *p_xl, *p_a1h, *p_a1l, *p_w1h, *p_w1l, *p_w2h, *p_w2l;
    cudaGetSymbolAddress((void**)&p_xh, g_xhi);
    cudaGetSymbolAddress((void**)&p_xl, g_xlo);
    cudaGetSymbolAddress((void**)&p_a1h, g_a1hi);
    cudaGetSymbolAddress((void**)&p_a1l, g_a1lo);
    cudaGetSymbolAddress((void**)&p_w1h, g_W1Thi);
    cudaGetSymbolAddress((void**)&p_w1l, g_W1Tlo);
    cudaGetSymbolAddress((void**)&p_w2h, g_W2Thi);
    cudaGetSymbolAddress((void**)&p_w2l, g_W2Tlo);

    cudaFuncSetAttribute(k_gemm_cp<KPAD1, 256>,
                         cudaFuncAttributeMaxDynamicSharedMemorySize, GSMEM_BYTES);
    cudaFuncSetAttribute(k_gemm_cp<256, 128>,
                         cudaFuncAttributeMaxDynamicSharedMemorySize, GSMEM_BYTES);

    const int MB = (NN + 127) / 128;  // 235

    k_init<<<(NN + 255) / 256, 256>>>();
    k_attn<<<NN, 128>>>(x, attn_W, attn_b);
    k_split<<<(256 * KPAD1 + 255) / 256, 256>>>(W1, W2);
    k_gemm_cp<KPAD1, 256><<<dim3(2, MB), 256, GSMEM_BYTES>>>(p_xh, p_xl, p_w1h, p_w1l, p_h1);
    k_alpha1<<<(NN * 32 + 255) / 256, 256>>>(as1, ad1);
    k_count<<<(NE + 255) / 256, 256>>>(ei);
    k_scan<<<1, 1024>>>();
    k_self<<<(NN + 255) / 256, 256>>>();
    k_scatter<<<(NE + 255) / 256, 256>>>(ei);
    k_agg1<<<(NN * 32 + 255) / 256, 256>>>(b1);
    k_gemm_cp<256, 128><<<dim3(1, MB), 256, GSMEM_BYTES>>>(p_a1h, p_a1l, p_w2h, p_w2l, p_h2);
    k_alpha2<<<(NN * 32 + 255) / 256, 256>>>(as2, ad2);
    k_agg2<<<(NN * 32 + 255) / 256, 256>>>(b2, batch);
    k_class<<<64, 128>>>(Wc1, bc1, Wc2, bc2, out);
}

// round 14
// speedup vs baseline: 1.1515x; 1.0187x over previous
#include <cuda_runtime.h>
#include <cuda_bf16.h>
#include <math.h>
#include <stdint.h>

#define NN    30000
#define NE    960000
#define ET    (NE + NN)
#define INDIM 4527
#define KPAD1 4544
#define HOGD  4464
#define HID   128
#define NG    64

// ---------------- scratch (device globals) ----------------------------------
__device__ float g_h1[NN * 256];
__device__ float g_as1[NN * 2];
__device__ float g_ad1[NN * 2];
__device__ float g_h2[NN * HID];
__device__ float g_as2[NN];
__device__ float g_ad2[NN];
__device__ int   g_cntN[NN];
__device__ int   g_indptr[NN + 1];
__device__ int   g_cursor[NN];
__device__ int   g_srcs[ET];
__device__ float g_pool[NG * HID];
__device__ int   g_gcnt[NG];
// pre-split bf16 operands (+128 row slack so OOB tile loads stay in-bounds)
__device__ __nv_bfloat16 g_xhi[(NN + 128) * KPAD1];
__device__ __nv_bfloat16 g_xlo[(NN + 128) * KPAD1];
__device__ __nv_bfloat16 g_a1hi[(NN + 128) * 256];
__device__ __nv_bfloat16 g_a1lo[(NN + 128) * 256];
__device__ __nv_bfloat16 g_W1Thi[256 * KPAD1];
__device__ __nv_bfloat16 g_W1Tlo[256 * KPAD1];
__device__ __nv_bfloat16 g_W2Thi[128 * 256];
__device__ __nv_bfloat16 g_W2Tlo[128 * 256];

// ---------------- helpers ---------------------------------------------------
__device__ __forceinline__ uint32_t smem_u32(const void* p) {
    uint32_t a;
    asm("{ .reg .u64 t; cvta.to.shared.u64 t, %1; cvt.u32.u64 %0, t; }"
        : "=r"(a) : "l"(p));
    return a;
}
__device__ __forceinline__ float warpSum(float v) {
#pragma unroll
    for (int o = 16; o; o >>= 1) v += __shfl_xor_sync(0xffffffffu, v, o);
    return v;
}
__device__ __forceinline__ float warpMax(float v) {
#pragma unroll
    for (int o = 16; o; o >>= 1) v = fmaxf(v, __shfl_xor_sync(0xffffffffu, v, o));
    return v;
}
__device__ __forceinline__ float lrelu(float v) { return v > 0.f ? v : 0.2f * v; }

__device__ __forceinline__ void mma16816(float c[4], const uint32_t a[4],
                                         uint32_t b0, uint32_t b1) {
    asm volatile(
        "mma.sync.aligned.m16n8k16.row.col.f32.bf16.bf16.f32 "
        "{%0,%1,%2,%3}, {%4,%5,%6,%7}, {%8,%9}, {%0,%1,%2,%3};"
        : "+f"(c[0]), "+f"(c[1]), "+f"(c[2]), "+f"(c[3])
        : "r"(a[0]), "r"(a[1]), "r"(a[2]), "r"(a[3]), "r"(b0), "r"(b1));
}
#define LDSM4(r0, r1, r2, r3, addr)                                           \
    asm volatile("ldmatrix.sync.aligned.m8n8.x4.shared.b16 {%0,%1,%2,%3}, [%4];" \
                 : "=r"(r0), "=r"(r1), "=r"(r2), "=r"(r3) : "r"(addr))
#define CP16(saddr, gaddr)                                                    \
    asm volatile("cp.async.cg.shared.global [%0], [%1], 16;"                  \
                 :: "r"(saddr), "l"(gaddr))
#define CP_COMMIT() asm volatile("cp.async.commit_group;" ::: "memory")
#define CP_WAIT1()  asm volatile("cp.async.wait_group 1;" ::: "memory")

__device__ __forceinline__ unsigned packsplit(float v0, float v1, float& r0, float& r1) {
    __nv_bfloat16 h0 = __float2bfloat16(v0), h1 = __float2bfloat16(v1);
    r0 = v0 - __bfloat162float(h0);
    r1 = v1 - __bfloat162float(h1);
    unsigned short a = *(unsigned short*)&h0, b = *(unsigned short*)&h1;
    return (unsigned)a | ((unsigned)b << 16);
}
__device__ __forceinline__ unsigned packlo(float v0, float v1) {
    __nv_bfloat16 h0 = __float2bfloat16(v0), h1 = __float2bfloat16(v1);
    unsigned short a = *(unsigned short*)&h0, b = *(unsigned short*)&h1;
    return (unsigned)a | ((unsigned)b << 16);
}

// ---------------- init -------------------------------------------------------
__global__ void k_init() {
    int i = blockIdx.x * blockDim.x + threadIdx.x;
    if (i < NN) g_cntN[i] = 1;
    if (i < NG * HID) g_pool[i] = 0.f;
    if (i < NG) g_gcnt[i] = 0;
}

// ---------------- attention gate + split gated x ----------------------------
__global__ void k_attn(const float* __restrict__ x,
                       const float* __restrict__ aW,
                       const float* __restrict__ ab) {
    int n = blockIdx.x;
    int t = threadIdx.x;  // 128
    const float* xr = x + (size_t)n * INDIM;
    float p0 = 0.f, p1 = 0.f;
    for (int k = t; k < INDIM; k += 128) {
        float v = xr[k];
        p0 += v * aW[2 * k];
        p1 += v * aW[2 * k + 1];
    }
    p0 = warpSum(p0);
    p1 = warpSum(p1);
    __shared__ float s0[4], s1[4];
    __shared__ float gg[2];
    if ((t & 31) == 0) { s0[t >> 5] = p0; s1[t >> 5] = p1; }
    __syncthreads();
    if (t == 0) {
        p0 = s0[0] + s0[1] + s0[2] + s0[3] + ab[0];
        p1 = s1[0] + s1[1] + s1[2] + s1[3] + ab[1];
        float m = fmaxf(p0, p1);
        float e0 = expf(p0 - m), e1 = expf(p1 - m);
        float inv = 1.f / (e0 + e1);
        gg[0] = e0 * inv;
        gg[1] = e1 * inv;
    }
    __syncthreads();
    float g0 = gg[0], g1 = gg[1];
    uint32_t* oh = (uint32_t*)(g_xhi + (size_t)n * KPAD1);
    uint32_t* ol = (uint32_t*)(g_xlo + (size_t)n * KPAD1);
    for (int p = t; p < KPAD1 / 2; p += 128) {
        int k = 2 * p;
        float v0 = 0.f, v1 = 0.f;
        if (k < INDIM)     v0 = xr[k] * ((k < HOGD) ? g0 : g1);
        if (k + 1 < INDIM) v1 = xr[k + 1] * ((k + 1 < HOGD) ? g0 : g1);
        float r0, r1;
        oh[p] = packsplit(v0, v1, r0, r1);
        ol[p] = packlo(r0, r1);
    }
}

// ---------------- weight split (+transpose to [n][k]) -----------------------
__global__ void k_split(const float* __restrict__ W1, const float* __restrict__ W2) {
    int i = blockIdx.x * blockDim.x + threadIdx.x;
    if (i < 256 * KPAD1) {
        int n = i / KPAD1, k = i % KPAD1;
        float v = (k < INDIM) ? W1[(size_t)k * 256 + n] : 0.f;
        __nv_bfloat16 h = __float2bfloat16(v);
        g_W1Thi[i] = h;
        g_W1Tlo[i] = __float2bfloat16(v - __bfloat162float(h));
    }
    if (i < 128 * 256) {
        int n = i / 256, k = i % 256;
        float v = W2[k * 128 + n];
        __nv_bfloat16 h = __float2bfloat16(v);
        g_W2Thi[i] = h;
        g_W2Tlo[i] = __float2bfloat16(v - __bfloat162float(h));
    }
}

// ---------------- split-bf16 tensor GEMM, 3-stage swizzled pipeline ---------
// (exact best-measured mainloop: WAIT1 / sync / cp / commit / ks loop,
//  term-inner MMA order)
#define PARTB   8192
#define STAGEB  (4 * PARTB)
#define GSMEM_BYTES (3 * STAGEB + 1024)

template <int KPADT, int NTOT>
__global__ __launch_bounds__(256, 2)
void k_gemm_cp(const __nv_bfloat16* __restrict__ Ahi,
               const __nv_bfloat16* __restrict__ Alo,
               const __nv_bfloat16* __restrict__ Bhi,
               const __nv_bfloat16* __restrict__ Blo,
               float* __restrict__ C) {
    constexpr int KT = KPADT / 32;
    extern __shared__ char smraw[];
    char* smb = (char*)(((uintptr_t)smraw + 1023) & ~(uintptr_t)1023);
    const uint32_t sb = smem_u32(smb);
    const int tid = threadIdx.x;
    const int l = tid & 31, w = tid >> 5;
    const int wm = w >> 2, wn = w & 3;       // 2x4 grid, 64x32 warp tiles
    const int bn = blockIdx.x * 128;
    const int bm = blockIdx.y * 128;

    const int crow = tid >> 1;
    const int cp0 = (tid & 1) * 2;
    const int csw = (crow >> 1) & 3;
    const uint32_t cs0 = (uint32_t)(crow * 64 + ((cp0 ^ csw) * 16));
    const uint32_t cs1 = (uint32_t)(crow * 64 + (((cp0 + 1) ^ csw) * 16));
    const __nv_bfloat16* aHiP = Ahi + (size_t)(bm + crow) * KPADT + cp0 * 8;
    const __nv_bfloat16* aLoP = Alo + (size_t)(bm + crow) * KPADT + cp0 * 8;
    const __nv_bfloat16* bHiP = Bhi + (size_t)(bn + crow) * KPADT + cp0 * 8;
    const __nv_bfloat16* bLoP = Blo + (size_t)(bn + crow) * KPADT + cp0 * 8;

    float acc[4][4][4];
#pragma unroll
    for (int i = 0; i < 4; i++)
#pragma unroll
        for (int j = 0; j < 4; j++)
#pragma unroll
            for (int q = 0; q < 4; q++) acc[i][j][q] = 0.f;

    auto cpStage = [&](int kt, int s) {
        const int k0 = kt * 32;
        uint32_t d = sb + s * STAGEB;
        CP16(d + cs0,             (const char*)(aHiP + k0));
        CP16(d + cs1,             (const char*)(aHiP + k0 + 8));
        CP16(d + PARTB + cs0,     (const char*)(aLoP + k0));
        CP16(d + PARTB + cs1,     (const char*)(aLoP + k0 + 8));
        CP16(d + 2 * PARTB + cs0, (const char*)(bHiP + k0));
        CP16(d + 2 * PARTB + cs1, (const char*)(bHiP + k0 + 8));
        CP16(d + 3 * PARTB + cs0, (const char*)(bLoP + k0));
        CP16(d + 3 * PARTB + cs1, (const char*)(bLoP + k0 + 8));
    };

    const uint32_t a_roff = (uint32_t)((wm * 64 + (l & 15)) * 64);
    const int sA = ((l & 15) >> 1) & 3;
    const int aC = (l >> 4) & 1;
    const uint32_t b_rl = (uint32_t)(((l >> 4) & 1) * 8 + (l & 7));
    const uint32_t b_roff = (uint32_t)((wn * 32) * 64) + b_rl * 64;
    const int sB = (int)((b_rl >> 1) & 3);
    const int bC = (l >> 3) & 1;

    cpStage(0, 0);
    CP_COMMIT();
    cpStage(1, 1);
    CP_COMMIT();

    int s = 0;
    for (int kt = 0; kt < KT; kt++) {
        CP_WAIT1();
        __syncthreads();
        if (kt + 2 < KT) {
            int ns = s + 2; if (ns >= 3) ns -= 3;
            cpStage(kt + 2, ns);
        }
        CP_COMMIT();

        const uint32_t stb = sb + s * STAGEB;
#pragma unroll
        for (int ks = 0; ks < 2; ks++) {
            const uint32_t ca = (uint32_t)(((2 * ks + aC) ^ sA) * 16);
            const uint32_t cb = (uint32_t)(((2 * ks + bC) ^ sB) * 16);
            uint32_t ah[4][4], al[4][4];
#pragma unroll
            for (int mt = 0; mt < 4; mt++) {
                uint32_t off = a_roff + mt * 1024 + ca;
                LDSM4(ah[mt][0], ah[mt][1], ah[mt][2], ah[mt][3], stb + off);
                LDSM4(al[mt][0], al[mt][1], al[mt][2], al[mt][3],
                      stb + PARTB + off);
            }
            uint32_t bh[4][2], bl[4][2];
#pragma unroll
            for (int pr = 0; pr < 2; pr++) {
                uint32_t off = b_roff + pr * 1024 + cb;
                LDSM4(bh[2 * pr][0], bh[2 * pr][1], bh[2 * pr + 1][0],
                      bh[2 * pr + 1][1], stb + 2 * PARTB + off);
                LDSM4(bl[2 * pr][0], bl[2 * pr][1], bl[2 * pr + 1][0],
                      bl[2 * pr + 1][1], stb + 3 * PARTB + off);
            }
#pragma unroll
            for (int nt = 0; nt < 4; nt++)
#pragma unroll
                for (int mt = 0; mt < 4; mt++) {
                    mma16816(acc[mt][nt], ah[mt], bh[nt][0], bh[nt][1]);
                    mma16816(acc[mt][nt], ah[mt], bl[nt][0], bl[nt][1]);
                    mma16816(acc[mt][nt], al[mt], bh[nt][0], bh[nt][1]);
                }
        }
        if (++s == 3) s = 0;
    }

    const int g = l >> 2, tq = l & 3;
#pragma unroll
    for (int mt = 0; mt < 4; mt++)
#pragma unroll
        for (int nt = 0; nt < 4; nt++) {
            int m0 = bm + wm * 64 + mt * 16 + g;
            int n = bn + wn * 32 + nt * 8 + 2 * tq;
            if (m0 < NN)
                *(float2*)&C[(size_t)m0 * NTOT + n] =
                    make_float2(acc[mt][nt][0], acc[mt][nt][1]);
            if (m0 + 8 < NN)
                *(float2*)&C[(size_t)(m0 + 8) * NTOT + n] =
                    make_float2(acc[mt][nt][2], acc[mt][nt][3]);
        }
}

// ---------------- alpha layer 1 ---------------------------------------------
__global__ void k_alpha1(const float* __restrict__ as1,
                         const float* __restrict__ ad1) {
    int w = (blockIdx.x * blockDim.x + threadIdx.x) >> 5;
    int l = threadIdx.x & 31;
    if (w >= NN) return;
    const float* hr = g_h1 + (size_t)w * 256;
    float ps0 = 0, pd0 = 0, ps1 = 0, pd1 = 0;
#pragma unroll
    for (int i = 0; i < 4; i++) {
        int d = l + i * 32;
        float v0 = hr[d], v1 = hr[128 + d];
        ps0 += v0 * as1[d];        pd0 += v0 * ad1[d];
        ps1 += v1 * as1[128 + d];  pd1 += v1 * ad1[128 + d];
    }
    ps0 = warpSum(ps0); pd0 = warpSum(pd0);
    ps1 = warpSum(ps1); pd1 = warpSum(pd1);
    if (l == 0) {
        g_as1[2 * w] = ps0; g_as1[2 * w + 1] = ps1;
        g_ad1[2 * w] = pd0; g_ad1[2 * w + 1] = pd1;
    }
}

// ---------------- CSR build --------------------------------------------------
__global__ void k_count(const int* __restrict__ ei) {
    int e = blockIdx.x * blockDim.x + threadIdx.x;
    if (e < NE) atomicAdd(&g_cntN[ei[NE + e]], 1);
}

__global__ void k_scan() {
    __shared__ int sh[1024];
    int t = threadIdx.x;
    const int CH = (NN + 1023) / 1024;
    int lo = t * CH, hi = min(lo + CH, NN);
    int s = 0;
    for (int i = lo; i < hi; i++) s += g_cntN[i];
    sh[t] = s;
    __syncthreads();
    for (int o = 1; o < 1024; o <<= 1) {
        int v = (t >= o) ? sh[t - o] : 0;
        __syncthreads();
        sh[t] += v;
        __syncthreads();
    }
    int run = (t == 0) ? 0 : sh[t - 1];
    for (int i = lo; i < hi; i++) { g_indptr[i] = run; run += g_cntN[i]; }
    if (t == 1023) g_indptr[NN] = sh[1023];
}

__global__ void k_self() {
    int i = blockIdx.x * blockDim.x + threadIdx.x;
    if (i < NN) { g_cursor[i] = 1; g_srcs[g_indptr[i]] = i; }
}

__global__ void k_scatter(const int* __restrict__ ei) {
    int e = blockIdx.x * blockDim.x + threadIdx.x;
    if (e < NE) {
        int s = ei[e], d = ei[NE + e];
        int pos = g_indptr[d] + atomicAdd(&g_cursor[d], 1);
        g_srcs[pos] = s;
    }
}

// ---------------- layer-1 aggregation (online softmax, 2 gather passes) -----
__global__ void k_agg1(const float* __restrict__ b1) {
    int w = (blockIdx.x * blockDim.x + threadIdx.x) >> 5;
    int l = threadIdx.x & 31;
    if (w >= NN) return;
    int beg = g_indptr[w], end = g_indptr[w + 1];
    float ad0 = g_ad1[2 * w], ad1 = g_ad1[2 * w + 1];

    // pass 1: online max + denom per lane
    float m0 = -1e30f, d0 = 0.f, m1 = -1e30f, d1 = 0.f;
    for (int j = beg + l; j < end; j += 32) {
        int s = g_srcs[j];
        float e0 = lrelu(g_as1[2 * s] + ad0);
        float e1 = lrelu(g_as1[2 * s + 1] + ad1);
        float nm0 = fmaxf(m0, e0);
        d0 = d0 * expf(m0 - nm0) + expf(e0 - nm0);
        m0 = nm0;
        float nm1 = fmaxf(m1, e1);
        d1 = d1 * expf(m1 - nm1) + expf(e1 - nm1);
        m1 = nm1;
    }
    // warp combine (m, d)
    float M0 = warpMax(m0), M1 = warpMax(m1);
    d0 = warpSum(d0 * expf(m0 - M0));
    d1 = warpSum(d1 * expf(m1 - M1));
    m0 = M0; m1 = M1;
    float i0 = 1.f / (d0 + 1e-16f), i1 = 1.f / (d1 + 1e-16f);

    // pass 2: weighted gather
    float acc[8] = {0, 0, 0, 0, 0, 0, 0, 0};
    for (int base = beg; base < end; base += 32) {
        int j = base + l;
        int s = 0; float w0 = 0.f, w1 = 0.f;
        if (j < end) {
            s = g_srcs[j];
            w0 = expf(lrelu(g_as1[2 * s] + ad0) - m0) * i0;
            w1 = expf(lrelu(g_as1[2 * s + 1] + ad1) - m1) * i1;
        }
        int cnt = min(32, end - base);
        for (int q = 0; q < cnt; q++) {
            int   sq  = __shfl_sync(0xffffffffu, s, q);
            float w0q = __shfl_sync(0xffffffffu, w0, q);
            float w1q = __shfl_sync(0xffffffffu, w1, q);
            const float* hp = g_h1 + (size_t)sq * 256 + l;
            acc[0] += w0q * hp[0];   acc[1] += w0q * hp[32];
            acc[2] += w0q * hp[64];  acc[3] += w0q * hp[96];
            acc[4] += w1q * hp[128]; acc[5] += w1q * hp[160];
            acc[6] += w1q * hp[192]; acc[7] += w1q * hp[224];
        }
    }
#pragma unroll
    for (int i = 0; i < 8; i++) {
        int d = l + i * 32;
        float v = acc[i] + b1[d];
        v = v > 0.f ? v : 0.f;
        __nv_bfloat16 h = __float2bfloat16(v);
        g_a1hi[(size_t)w * 256 + d] = h;
        g_a1lo[(size_t)w * 256 + d] = __float2bfloat16(v - __bfloat162float(h));
    }
}

// ---------------- alpha layer 2 ---------------------------------------------
__global__ void k_alpha2(const float* __restrict__ as2,
                         const float* __restrict__ ad2) {
    int w = (blockIdx.x * blockDim.x + threadIdx.x) >> 5;
    int l = threadIdx.x & 31;
    if (w >= NN) return;
    const float* hr = g_h2 + (size_t)w * 128;
    float ps = 0.f, pd = 0.f;
#pragma unroll
    for (int i = 0; i < 4; i++) {
        int d = l + i * 32;
        float v = hr[d];
        ps += v * as2[d];
        pd += v * ad2[d];
    }
    ps = warpSum(ps); pd = warpSum(pd);
    if (l == 0) { g_as2[w] = ps; g_ad2[w] = pd; }
}

// ---------------- layer-2 aggregation + pooling (online softmax) -------------
__global__ void k_agg2(const float* __restrict__ b2,
                       const int* __restrict__ batch) {
    int w = (blockIdx.x * blockDim.x + threadIdx.x) >> 5;
    int l = threadIdx.x & 31;
    if (w >= NN) return;
    int beg = g_indptr[w], end = g_indptr[w + 1];
    float ad = g_ad2[w];

    float m = -1e30f, den = 0.f;
    for (int j = beg + l; j < end; j += 32) {
        float e = lrelu(g_as2[g_srcs[j]] + ad);
        float nm = fmaxf(m, e);
        den = den * expf(m - nm) + expf(e - nm);
        m = nm;
    }
    float M = warpMax(m);
    den = warpSum(den * expf(m - M));
    m = M;
    float inv = 1.f / (den + 1e-16f);

    float acc[4] = {0, 0, 0, 0};
    for (int base = beg; base < end; base += 32) {
        int j = base + l;
        int s = 0; float ww = 0.f;
        if (j < end) {
            s = g_srcs[j];
            ww = expf(lrelu(g_as2[s] + ad) - m) * inv;
        }
        int cnt = min(32, end - base);
        for (int q = 0; q < cnt; q++) {
            int   sq = __shfl_sync(0xffffffffu, s, q);
            float wq = __shfl_sync(0xffffffffu, ww, q);
            const float* hp = g_h2 + (size_t)sq * 128 + l;
            acc[0] += wq * hp[0];  acc[1] += wq * hp[32];
            acc[2] += wq * hp[64]; acc[3] += wq * hp[96];
        }
    }
    int b = batch[w];
#pragma unroll
    for (int i = 0; i < 4; i++) {
        int d = l + i * 32;
        float v = acc[i] + b2[d];
        v = v > 0.f ? v : 0.f;
        atomicAdd(&g_pool[b * 128 + d], v);
    }
    if (l == 0) atomicAdd(&g_gcnt[b], 1);
}

// ---------------- classifier head -------------------------------------------
__global__ void k_class(const float* __restrict__ Wc1, const float* __restrict__ bc1,
                        const float* __restrict__ Wc2, const float* __restrict__ bc2,
                        float* __restrict__ out) {
    int g = blockIdx.x, t = threadIdx.x;
    __shared__ float p[128];
    __shared__ float z[64];
    float c = fmaxf((float)g_gcnt[g], 1.f);
    p[t] = g_pool[g * 128 + t] / c;
    __syncthreads();
    if (t < 64) {
        float s = bc1[t];
        for (int i = 0; i < 128; i++) s += p[i] * Wc1[i * 64 + t];
        z[t] = s > 0.f ? s : 0.f;
    }
    __syncthreads();
    if (t < 4) {
        float s = bc2[t];
        for (int i = 0; i < 64; i++) s += z[i] * Wc2[i * 4 + t];
        out[g * 4 + t] = s;
    }
}

// ---------------- launch -----------------------------------------------------
extern "C" void kernel_launch(void* const* d_in, const int* in_sizes, int n_in,
                              void* d_out, int out_size) {
    const float* x      = (const float*)d_in[0];
    const int*   ei     = (const int*)d_in[1];
    const int*   batch  = (const int*)d_in[2];
    const float* attn_W = (const float*)d_in[3];
    const float* attn_b = (const float*)d_in[4];
    const float* W1     = (const float*)d_in[5];
    const float* as1    = (const float*)d_in[6];
    const float* ad1    = (const float*)d_in[7];
    const float* b1     = (const float*)d_in[8];
    const float* W2     = (const float*)d_in[9];
    const float* as2    = (const float*)d_in[10];
    const float* ad2    = (const float*)d_in[11];
    const float* b2     = (const float*)d_in[12];
    const float* Wc1    = (const float*)d_in[13];
    const float* bc1    = (const float*)d_in[14];
    const float* Wc2    = (const float*)d_in[15];
    const float* bc2    = (const float*)d_in[16];
    float* out = (float*)d_out;

    float* p_h1;   cudaGetSymbolAddress((void**)&p_h1, g_h1);
    float* p_h2;   cudaGetSymbolAddress((void**)&p_h2, g_h2);
    __nv_bfloat16 *p_xh, *p_xl, *p_a1h, *p_a1l, *p_w1h, *p_w1l, *p_w2h, *p_w2l;
    cudaGetSymbolAddress((void**)&p_xh, g_xhi);
    cudaGetSymbolAddress((void**)&p_xl, g_xlo);
    cudaGetSymbolAddress((void**)&p_a1h, g_a1hi);
    cudaGetSymbolAddress((void**)&p_a1l, g_a1lo);
    cudaGetSymbolAddress((void**)&p_w1h, g_W1Thi);
    cudaGetSymbolAddress((void**)&p_w1l, g_W1Tlo);
    cudaGetSymbolAddress((void**)&p_w2h, g_W2Thi);
    cudaGetSymbolAddress((void**)&p_w2l, g_W2Tlo);

    cudaFuncSetAttribute(k_gemm_cp<KPAD1, 256>,
                         cudaFuncAttributeMaxDynamicSharedMemorySize, GSMEM_BYTES);
    cudaFuncSetAttribute(k_gemm_cp<256, 128>,
                         cudaFuncAttributeMaxDynamicSharedMemorySize, GSMEM_BYTES);

    const int MB = (NN + 127) / 128;  // 235

    k_init<<<(NN + 255) / 256, 256>>>();
    k_attn<<<NN, 128>>>(x, attn_W, attn_b);
    k_split<<<(256 * KPAD1 + 255) / 256, 256>>>(W1, W2);
    k_gemm_cp<KPAD1, 256><<<dim3(2, MB), 256, GSMEM_BYTES>>>(p_xh, p_xl, p_w1h, p_w1l, p_h1);
    k_alpha1<<<(NN * 32 + 255) / 256, 256>>>(as1, ad1);
    k_count<<<(NE + 255) / 256, 256>>>(ei);
    k_scan<<<1, 1024>>>();
    k_self<<<(NN + 255) / 256, 256>>>();
    k_scatter<<<(NE + 255) / 256, 256>>>(ei);
    k_agg1<<<(NN * 32 + 255) / 256, 256>>>(b1);
    k_gemm_cp<256, 128><<<dim3(1, MB), 256, GSMEM_BYTES>>>(p_a1h, p_a1l, p_w2h, p_w2l, p_h2);
    k_alpha2<<<(NN * 32 + 255) / 256, 256>>>(as2, ad2);
    k_agg2<<<(NN * 32 + 255) / 256, 256>>>(b2, batch);
    k_class<<<64, 128>>>(Wc1, bc1, Wc2, bc2, out);
}

// round 16
// speedup vs baseline: 1.1944x; 1.0372x over previous
#include <cuda_runtime.h>
#include <cuda_bf16.h>
#include <math.h>
#include <stdint.h>

#define NN    30000
#define NE    960000
#define ET    (NE + NN)
#define INDIM 4527
#define KPAD1 4544
#define HOGD  4464
#define HID   128
#define NG    64

// ---------------- scratch (device globals) ----------------------------------
__device__ float g_h1[NN * 256];
__device__ float g_as1[NN * 2];
__device__ float g_ad1[NN * 2];
__device__ float g_h2[NN * HID];
__device__ float g_as2[NN];
__device__ float g_ad2[NN];
__device__ int   g_cntN[NN];
__device__ int   g_indptr[NN + 1];
__device__ int   g_cursor[NN];
__device__ int   g_srcs[ET];
__device__ float g_pool[NG * HID];
__device__ int   g_gcnt[NG];
// pre-split bf16 operands (+128 row slack so OOB tile loads stay in-bounds)
__device__ __nv_bfloat16 g_xhi[(NN + 128) * KPAD1];
__device__ __nv_bfloat16 g_xlo[(NN + 128) * KPAD1];
__device__ __nv_bfloat16 g_a1hi[(NN + 128) * 256];
__device__ __nv_bfloat16 g_a1lo[(NN + 128) * 256];
__device__ __nv_bfloat16 g_W1Thi[256 * KPAD1];
__device__ __nv_bfloat16 g_W1Tlo[256 * KPAD1];
__device__ __nv_bfloat16 g_W2Thi[128 * 256];
__device__ __nv_bfloat16 g_W2Tlo[128 * 256];

// ---------------- helpers ---------------------------------------------------
__device__ __forceinline__ uint32_t smem_u32(const void* p) {
    uint32_t a;
    asm("{ .reg .u64 t; cvta.to.shared.u64 t, %1; cvt.u32.u64 %0, t; }"
        : "=r"(a) : "l"(p));
    return a;
}
__device__ __forceinline__ float warpSum(float v) {
#pragma unroll
    for (int o = 16; o; o >>= 1) v += __shfl_xor_sync(0xffffffffu, v, o);
    return v;
}
__device__ __forceinline__ float warpMax(float v) {
#pragma unroll
    for (int o = 16; o; o >>= 1) v = fmaxf(v, __shfl_xor_sync(0xffffffffu, v, o));
    return v;
}
__device__ __forceinline__ float lrelu(float v) { return v > 0.f ? v : 0.2f * v; }

__device__ __forceinline__ void mma16816(float c[4], const uint32_t a[4],
                                         uint32_t b0, uint32_t b1) {
    asm volatile(
        "mma.sync.aligned.m16n8k16.row.col.f32.bf16.bf16.f32 "
        "{%0,%1,%2,%3}, {%4,%5,%6,%7}, {%8,%9}, {%0,%1,%2,%3};"
        : "+f"(c[0]), "+f"(c[1]), "+f"(c[2]), "+f"(c[3])
        : "r"(a[0]), "r"(a[1]), "r"(a[2]), "r"(a[3]), "r"(b0), "r"(b1));
}
#define LDSM4(r0, r1, r2, r3, addr)                                           \
    asm volatile("ldmatrix.sync.aligned.m8n8.x4.shared.b16 {%0,%1,%2,%3}, [%4];" \
                 : "=r"(r0), "=r"(r1), "=r"(r2), "=r"(r3) : "r"(addr))
#define CP16(saddr, gaddr)                                                    \
    asm volatile("cp.async.cg.shared.global [%0], [%1], 16;"                  \
                 :: "r"(saddr), "l"(gaddr))
#define CP_COMMIT() asm volatile("cp.async.commit_group;" ::: "memory")
#define CP_WAIT1()  asm volatile("cp.async.wait_group 1;" ::: "memory")

__device__ __forceinline__ unsigned packsplit(float v0, float v1, float& r0, float& r1) {
    __nv_bfloat16 h0 = __float2bfloat16(v0), h1 = __float2bfloat16(v1);
    r0 = v0 - __bfloat162float(h0);
    r1 = v1 - __bfloat162float(h1);
    unsigned short a = *(unsigned short*)&h0, b = *(unsigned short*)&h1;
    return (unsigned)a | ((unsigned)b << 16);
}
__device__ __forceinline__ unsigned packlo(float v0, float v1) {
    __nv_bfloat16 h0 = __float2bfloat16(v0), h1 = __float2bfloat16(v1);
    unsigned short a = *(unsigned short*)&h0, b = *(unsigned short*)&h1;
    return (unsigned)a | ((unsigned)b << 16);
}

// ---------------- init -------------------------------------------------------
__global__ void k_init() {
    int i = blockIdx.x * blockDim.x + threadIdx.x;
    if (i < NN) g_cntN[i] = 1;
    if (i < NG * HID) g_pool[i] = 0.f;
    if (i < NG) g_gcnt[i] = 0;
}

// ---------------- attention gate + split gated x ----------------------------
__global__ void k_attn(const float* __restrict__ x,
                       const float* __restrict__ aW,
                       const float* __restrict__ ab) {
    int n = blockIdx.x;
    int t = threadIdx.x;  // 128
    const float* xr = x + (size_t)n * INDIM;
    float p0 = 0.f, p1 = 0.f;
    for (int k = t; k < INDIM; k += 128) {
        float v = xr[k];
        p0 += v * aW[2 * k];
        p1 += v * aW[2 * k + 1];
    }
    p0 = warpSum(p0);
    p1 = warpSum(p1);
    __shared__ float s0[4], s1[4];
    __shared__ float gg[2];
    if ((t & 31) == 0) { s0[t >> 5] = p0; s1[t >> 5] = p1; }
    __syncthreads();
    if (t == 0) {
        p0 = s0[0] + s0[1] + s0[2] + s0[3] + ab[0];
        p1 = s1[0] + s1[1] + s1[2] + s1[3] + ab[1];
        float m = fmaxf(p0, p1);
        float e0 = expf(p0 - m), e1 = expf(p1 - m);
        float inv = 1.f / (e0 + e1);
        gg[0] = e0 * inv;
        gg[1] = e1 * inv;
    }
    __syncthreads();
    float g0 = gg[0], g1 = gg[1];
    uint32_t* oh = (uint32_t*)(g_xhi + (size_t)n * KPAD1);
    uint32_t* ol = (uint32_t*)(g_xlo + (size_t)n * KPAD1);
    for (int p = t; p < KPAD1 / 2; p += 128) {
        int k = 2 * p;
        float v0 = 0.f, v1 = 0.f;
        if (k < INDIM)     v0 = xr[k] * ((k < HOGD) ? g0 : g1);
        if (k + 1 < INDIM) v1 = xr[k + 1] * ((k + 1 < HOGD) ? g0 : g1);
        float r0, r1;
        oh[p] = packsplit(v0, v1, r0, r1);
        ol[p] = packlo(r0, r1);
    }
}

// ---------------- weight split (+transpose to [n][k]) -----------------------
__global__ void k_split(const float* __restrict__ W1, const float* __restrict__ W2) {
    int i = blockIdx.x * blockDim.x + threadIdx.x;
    if (i < 256 * KPAD1) {
        int n = i / KPAD1, k = i % KPAD1;
        float v = (k < INDIM) ? W1[(size_t)k * 256 + n] : 0.f;
        __nv_bfloat16 h = __float2bfloat16(v);
        g_W1Thi[i] = h;
        g_W1Tlo[i] = __float2bfloat16(v - __bfloat162float(h));
    }
    if (i < 128 * 256) {
        int n = i / 256, k = i % 256;
        float v = W2[k * 128 + n];
        __nv_bfloat16 h = __float2bfloat16(v);
        g_W2Thi[i] = h;
        g_W2Tlo[i] = __float2bfloat16(v - __bfloat162float(h));
    }
}

// ---------------- split-bf16 GEMM, 128x64 tile, 3 CTAs/SM, 3-stage ----------
// 256 threads, warp tile 32x32 (4x2 warp grid). acc=32 regs/thread.
// Stage = Ahi(8K)|Alo(8K)|Bhi(4K)|Blo(4K) = 24KB; 3 stages = 72KB.
#define PARTA2  8192
#define PARTB2  4096
#define STAGE2  (2 * PARTA2 + 2 * PARTB2)
#define GSMEM_BYTES (3 * STAGE2 + 1024)

template <int KPADT, int NTOT>
__global__ __launch_bounds__(256, 3)
void k_gemm_cp(const __nv_bfloat16* __restrict__ Ahi,
               const __nv_bfloat16* __restrict__ Alo,
               const __nv_bfloat16* __restrict__ Bhi,
               const __nv_bfloat16* __restrict__ Blo,
               float* __restrict__ C) {
    constexpr int KT = KPADT / 32;
    extern __shared__ char smraw[];
    char* smb = (char*)(((uintptr_t)smraw + 1023) & ~(uintptr_t)1023);
    const uint32_t sb = smem_u32(smb);
    const int tid = threadIdx.x;
    const int l = tid & 31, w = tid >> 5;
    const int wm = w & 3, wn = w >> 2;       // 4x2 grid, 32x32 warp tiles
    const int bn = blockIdx.x * 64;
    const int bm = blockIdx.y * 128;

    // cp.async A: row tid>>1 (0..127), chunk pair (tid&1)*2
    const int arow = tid >> 1;
    const int acp = (tid & 1) * 2;
    const int asw = (arow >> 1) & 3;
    const uint32_t as0 = (uint32_t)(arow * 64 + ((acp ^ asw) * 16));
    const uint32_t as1o = (uint32_t)(arow * 64 + (((acp + 1) ^ asw) * 16));
    // cp.async B: row tid>>2 (0..63), single chunk tid&3
    const int brow = tid >> 2;
    const int bcp = tid & 3;
    const int bsw = (brow >> 1) & 3;
    const uint32_t bs0 = (uint32_t)(brow * 64 + ((bcp ^ bsw) * 16));

    const __nv_bfloat16* aHiP = Ahi + (size_t)(bm + arow) * KPADT + acp * 8;
    const __nv_bfloat16* aLoP = Alo + (size_t)(bm + arow) * KPADT + acp * 8;
    const __nv_bfloat16* bHiP = Bhi + (size_t)(bn + brow) * KPADT + bcp * 8;
    const __nv_bfloat16* bLoP = Blo + (size_t)(bn + brow) * KPADT + bcp * 8;

    float acc[2][4][4];
#pragma unroll
    for (int i = 0; i < 2; i++)
#pragma unroll
        for (int j = 0; j < 4; j++)
#pragma unroll
            for (int q = 0; q < 4; q++) acc[i][j][q] = 0.f;

    auto cpStage = [&](int kt, int s) {
        const int k0 = kt * 32;
        uint32_t d = sb + s * STAGE2;
        CP16(d + as0,                  (const char*)(aHiP + k0));
        CP16(d + as1o,                 (const char*)(aHiP + k0 + 8));
        CP16(d + PARTA2 + as0,         (const char*)(aLoP + k0));
        CP16(d + PARTA2 + as1o,        (const char*)(aLoP + k0 + 8));
        CP16(d + 2 * PARTA2 + bs0,     (const char*)(bHiP + k0));
        CP16(d + 2 * PARTA2 + PARTB2 + bs0, (const char*)(bLoP + k0));
    };

    // LDSM address components
    const uint32_t a_roff = (uint32_t)((wm * 32 + (l & 15)) * 64);
    const int sA = ((l & 15) >> 1) & 3;
    const int aC = (l >> 4) & 1;
    const uint32_t b_rl = (uint32_t)(((l >> 4) & 1) * 8 + (l & 7));
    const uint32_t b_roff = (uint32_t)((wn * 32 + b_rl) * 64);
    const int sB = (int)((b_rl >> 1) & 3);
    const int bC = (l >> 3) & 1;

    cpStage(0, 0);
    CP_COMMIT();
    cpStage(1, 1);
    CP_COMMIT();

    int s = 0;
    for (int kt = 0; kt < KT; kt++) {
        CP_WAIT1();
        __syncthreads();
        if (kt + 2 < KT) {
            int ns = s + 2; if (ns >= 3) ns -= 3;
            cpStage(kt + 2, ns);
        }
        CP_COMMIT();

        const uint32_t stb = sb + s * STAGE2;
#pragma unroll
        for (int ks = 0; ks < 2; ks++) {
            const uint32_t ca = (uint32_t)(((2 * ks + aC) ^ sA) * 16);
            const uint32_t cb = (uint32_t)(((2 * ks + bC) ^ sB) * 16);
            uint32_t ah[2][4], al[2][4];
#pragma unroll
            for (int mt = 0; mt < 2; mt++) {
                uint32_t off = a_roff + mt * 1024 + ca;
                LDSM4(ah[mt][0], ah[mt][1], ah[mt][2], ah[mt][3], stb + off);
                LDSM4(al[mt][0], al[mt][1], al[mt][2], al[mt][3],
                      stb + PARTA2 + off);
            }
            uint32_t bh[4][2], bl[4][2];
#pragma unroll
            for (int pr = 0; pr < 2; pr++) {
                uint32_t off = b_roff + pr * 1024 + cb;
                LDSM4(bh[2 * pr][0], bh[2 * pr][1], bh[2 * pr + 1][0],
                      bh[2 * pr + 1][1], stb + 2 * PARTA2 + off);
                LDSM4(bl[2 * pr][0], bl[2 * pr][1], bl[2 * pr + 1][0],
                      bl[2 * pr + 1][1], stb + 2 * PARTA2 + PARTB2 + off);
            }
#pragma unroll
            for (int nt = 0; nt < 4; nt++)
#pragma unroll
                for (int mt = 0; mt < 2; mt++) {
                    mma16816(acc[mt][nt], ah[mt], bh[nt][0], bh[nt][1]);
                    mma16816(acc[mt][nt], ah[mt], bl[nt][0], bl[nt][1]);
                    mma16816(acc[mt][nt], al[mt], bh[nt][0], bh[nt][1]);
                }
        }
        if (++s == 3) s = 0;
    }

    const int g = l >> 2, tq = l & 3;
#pragma unroll
    for (int mt = 0; mt < 2; mt++)
#pragma unroll
        for (int nt = 0; nt < 4; nt++) {
            int m0 = bm + wm * 32 + mt * 16 + g;
            int n = bn + wn * 32 + nt * 8 + 2 * tq;
            if (m0 < NN)
                *(float2*)&C[(size_t)m0 * NTOT + n] =
                    make_float2(acc[mt][nt][0], acc[mt][nt][1]);
            if (m0 + 8 < NN)
                *(float2*)&C[(size_t)(m0 + 8) * NTOT + n] =
                    make_float2(acc[mt][nt][2], acc[mt][nt][3]);
        }
}

// ---------------- alpha layer 1 ---------------------------------------------
__global__ void k_alpha1(const float* __restrict__ as1,
                         const float* __restrict__ ad1) {
    int w = (blockIdx.x * blockDim.x + threadIdx.x) >> 5;
    int l = threadIdx.x & 31;
    if (w >= NN) return;
    const float* hr = g_h1 + (size_t)w * 256;
    float ps0 = 0, pd0 = 0, ps1 = 0, pd1 = 0;
#pragma unroll
    for (int i = 0; i < 4; i++) {
        int d = l + i * 32;
        float v0 = hr[d], v1 = hr[128 + d];
        ps0 += v0 * as1[d];        pd0 += v0 * ad1[d];
        ps1 += v1 * as1[128 + d];  pd1 += v1 * ad1[128 + d];
    }
    ps0 = warpSum(ps0); pd0 = warpSum(pd0);
    ps1 = warpSum(ps1); pd1 = warpSum(pd1);
    if (l == 0) {
        g_as1[2 * w] = ps0; g_as1[2 * w + 1] = ps1;
        g_ad1[2 * w] = pd0; g_ad1[2 * w + 1] = pd1;
    }
}

// ---------------- CSR build --------------------------------------------------
__global__ void k_count(const int* __restrict__ ei) {
    int e = blockIdx.x * blockDim.x + threadIdx.x;
    if (e < NE) atomicAdd(&g_cntN[ei[NE + e]], 1);
}

__global__ void k_scan() {
    __shared__ int sh[1024];
    int t = threadIdx.x;
    const int CH = (NN + 1023) / 1024;
    int lo = t * CH, hi = min(lo + CH, NN);
    int s = 0;
    for (int i = lo; i < hi; i++) s += g_cntN[i];
    sh[t] = s;
    __syncthreads();
    for (int o = 1; o < 1024; o <<= 1) {
        int v = (t >= o) ? sh[t - o] : 0;
        __syncthreads();
        sh[t] += v;
        __syncthreads();
    }
    int run = (t == 0) ? 0 : sh[t - 1];
    for (int i = lo; i < hi; i++) { g_indptr[i] = run; run += g_cntN[i]; }
    if (t == 1023) g_indptr[NN] = sh[1023];
}

__global__ void k_self() {
    int i = blockIdx.x * blockDim.x + threadIdx.x;
    if (i < NN) { g_cursor[i] = 1; g_srcs[g_indptr[i]] = i; }
}

__global__ void k_scatter(const int* __restrict__ ei) {
    int e = blockIdx.x * blockDim.x + threadIdx.x;
    if (e < NE) {
        int s = ei[e], d = ei[NE + e];
        int pos = g_indptr[d] + atomicAdd(&g_cursor[d], 1);
        g_srcs[pos] = s;
    }
}

// ---------------- layer-1 aggregation (online softmax, 2 gather passes) -----
__global__ void k_agg1(const float* __restrict__ b1) {
    int w = (blockIdx.x * blockDim.x + threadIdx.x) >> 5;
    int l = threadIdx.x & 31;
    if (w >= NN) return;
    int beg = g_indptr[w], end = g_indptr[w + 1];
    float ad0 = g_ad1[2 * w], ad1 = g_ad1[2 * w + 1];

    float m0 = -1e30f, d0 = 0.f, m1 = -1e30f, d1 = 0.f;
    for (int j = beg + l; j < end; j += 32) {
        int s = g_srcs[j];
        float e0 = lrelu(g_as1[2 * s] + ad0);
        float e1 = lrelu(g_as1[2 * s + 1] + ad1);
        float nm0 = fmaxf(m0, e0);
        d0 = d0 * expf(m0 - nm0) + expf(e0 - nm0);
        m0 = nm0;
        float nm1 = fmaxf(m1, e1);
        d1 = d1 * expf(m1 - nm1) + expf(e1 - nm1);
        m1 = nm1;
    }
    float M0 = warpMax(m0), M1 = warpMax(m1);
    d0 = warpSum(d0 * expf(m0 - M0));
    d1 = warpSum(d1 * expf(m1 - M1));
    m0 = M0; m1 = M1;
    float i0 = 1.f / (d0 + 1e-16f), i1 = 1.f / (d1 + 1e-16f);

    float acc[8] = {0, 0, 0, 0, 0, 0, 0, 0};
    for (int base = beg; base < end; base += 32) {
        int j = base + l;
        int s = 0; float w0 = 0.f, w1 = 0.f;
        if (j < end) {
            s = g_srcs[j];
            w0 = expf(lrelu(g_as1[2 * s] + ad0) - m0) * i0;
            w1 = expf(lrelu(g_as1[2 * s + 1] + ad1) - m1) * i1;
        }
        int cnt = min(32, end - base);
        for (int q = 0; q < cnt; q++) {
            int   sq  = __shfl_sync(0xffffffffu, s, q);
            float w0q = __shfl_sync(0xffffffffu, w0, q);
            float w1q = __shfl_sync(0xffffffffu, w1, q);
            const float* hp = g_h1 + (size_t)sq * 256 + l;
            acc[0] += w0q * hp[0];   acc[1] += w0q * hp[32];
            acc[2] += w0q * hp[64];  acc[3] += w0q * hp[96];
            acc[4] += w1q * hp[128]; acc[5] += w1q * hp[160];
            acc[6] += w1q * hp[192]; acc[7] += w1q * hp[224];
        }
    }
#pragma unroll
    for (int i = 0; i < 8; i++) {
        int d = l + i * 32;
        float v = acc[i] + b1[d];
        v = v > 0.f ? v : 0.f;
        __nv_bfloat16 h = __float2bfloat16(v);
        g_a1hi[(size_t)w * 256 + d] = h;
        g_a1lo[(size_t)w * 256 + d] = __float2bfloat16(v - __bfloat162float(h));
    }
}

// ---------------- alpha layer 2 ---------------------------------------------
__global__ void k_alpha2(const float* __restrict__ as2,
                         const float* __restrict__ ad2) {
    int w = (blockIdx.x * blockDim.x + threadIdx.x) >> 5;
    int l = threadIdx.x & 31;
    if (w >= NN) return;
    const float* hr = g_h2 + (size_t)w * 128;
    float ps = 0.f, pd = 0.f;
#pragma unroll
    for (int i = 0; i < 4; i++) {
        int d = l + i * 32;
        float v = hr[d];
        ps += v * as2[d];
        pd += v * ad2[d];
    }
    ps = warpSum(ps); pd = warpSum(pd);
    if (l == 0) { g_as2[w] = ps; g_ad2[w] = pd; }
}

// ---------------- layer-2 aggregation + pooling (online softmax) -------------
__global__ void k_agg2(const float* __restrict__ b2,
                       const int* __restrict__ batch) {
    int w = (blockIdx.x * blockDim.x + threadIdx.x) >> 5;
    int l = threadIdx.x & 31;
    if (w >= NN) return;
    int beg = g_indptr[w], end = g_indptr[w + 1];
    float ad = g_ad2[w];

    float m = -1e30f, den = 0.f;
    for (int j = beg + l; j < end; j += 32) {
        float e = lrelu(g_as2[g_srcs[j]] + ad);
        float nm = fmaxf(m, e);
        den = den * expf(m - nm) + expf(e - nm);
        m = nm;
    }
    float M = warpMax(m);
    den = warpSum(den * expf(m - M));
    m = M;
    float inv = 1.f / (den + 1e-16f);

    float acc[4] = {0, 0, 0, 0};
    for (int base = beg; base < end; base += 32) {
        int j = base + l;
        int s = 0; float ww = 0.f;
        if (j < end) {
            s = g_srcs[j];
            ww = expf(lrelu(g_as2[s] + ad) - m) * inv;
        }
        int cnt = min(32, end - base);
        for (int q = 0; q < cnt; q++) {
            int   sq = __shfl_sync(0xffffffffu, s, q);
            float wq = __shfl_sync(0xffffffffu, ww, q);
            const float* hp = g_h2 + (size_t)sq * 128 + l;
            acc[0] += wq * hp[0];  acc[1] += wq * hp[32];
            acc[2] += wq * hp[64]; acc[3] += wq * hp[96];
        }
    }
    int b = batch[w];
#pragma unroll
    for (int i = 0; i < 4; i++) {
        int d = l + i * 32;
        float v = acc[i] + b2[d];
        v = v > 0.f ? v : 0.f;
        atomicAdd(&g_pool[b * 128 + d], v);
    }
    if (l == 0) atomicAdd(&g_gcnt[b], 1);
}

// ---------------- classifier head -------------------------------------------
__global__ void k_class(const float* __restrict__ Wc1, const float* __restrict__ bc1,
                        const float* __restrict__ Wc2, const float* __restrict__ bc2,
                        float* __restrict__ out) {
    int g = blockIdx.x, t = threadIdx.x;
    __shared__ float p[128];
    __shared__ float z[64];
    float c = fmaxf((float)g_gcnt[g], 1.f);
    p[t] = g_pool[g * 128 + t] / c;
    __syncthreads();
    if (t < 64) {
        float s = bc1[t];
        for (int i = 0; i < 128; i++) s += p[i] * Wc1[i * 64 + t];
        z[t] = s > 0.f ? s : 0.f;
    }
    __syncthreads();
    if (t < 4) {
        float s = bc2[t];
        for (int i = 0; i < 64; i++) s += z[i] * Wc2[i * 4 + t];
        out[g * 4 + t] = s;
    }
}

// ---------------- launch -----------------------------------------------------
extern "C" void kernel_launch(void* const* d_in, const int* in_sizes, int n_in,
                              void* d_out, int out_size) {
    const float* x      = (const float*)d_in[0];
    const int*   ei     = (const int*)d_in[1];
    const int*   batch  = (const int*)d_in[2];
    const float* attn_W = (const float*)d_in[3];
    const float* attn_b = (const float*)d_in[4];
    const float* W1     = (const float*)d_in[5];
    const float* as1    = (const float*)d_in[6];
    const float* ad1    = (const float*)d_in[7];
    const float* b1     = (const float*)d_in[8];
    const float* W2     = (const float*)d_in[9];
    const float* as2    = (const float*)d_in[10];
    const float* ad2    = (const float*)d_in[11];
    const float* b2     = (const float*)d_in[12];
    const float* Wc1    = (const float*)d_in[13];
    const float* bc1    = (const float*)d_in[14];
    const float* Wc2    = (const float*)d_in[15];
    const float* bc2    = (const float*)d_in[16];
    float* out = (float*)d_out;

    float* p_h1;   cudaGetSymbolAddress((void**)&p_h1, g_h1);
    float* p_h2;   cudaGetSymbolAddress((void**)&p_h2, g_h2);
    __nv_bfloat16 *p_xh, *p_xl, *p_a1h, *p_a1l, *p_w1h, *p_w1l, *p_w2h, *p_w2l;
    cudaGetSymbolAddress((void**)&p_xh, g_xhi);
    cudaGetSymbolAddress((void**)&p_xl, g_xlo);
    cudaGetSymbolAddress((void**)&p_a1h, g_a1hi);
    cudaGetSymbolAddress((void**)&p_a1l, g_a1lo);
    cudaGetSymbolAddress((void**)&p_w1h, g_W1Thi);
    cudaGetSymbolAddress((void**)&p_w1l, g_W1Tlo);
    cudaGetSymbolAddress((void**)&p_w2h, g_W2Thi);
    cudaGetSymbolAddress((void**)&p_w2l, g_W2Tlo);

    cudaFuncSetAttribute(k_gemm_cp<KPAD1, 256>,
                         cudaFuncAttributeMaxDynamicSharedMemorySize, GSMEM_BYTES);
    cudaFuncSetAttribute(k_gemm_cp<256, 128>,
                         cudaFuncAttributeMaxDynamicSharedMemorySize, GSMEM_BYTES);

    const int MB = (NN + 127) / 128;  // 235

    k_init<<<(NN + 255) / 256, 256>>>();
    k_attn<<<NN, 128>>>(x, attn_W, attn_b);
    k_split<<<(256 * KPAD1 + 255) / 256, 256>>>(W1, W2);
    k_gemm_cp<KPAD1, 256><<<dim3(4, MB), 256, GSMEM_BYTES>>>(p_xh, p_xl, p_w1h, p_w1l, p_h1);
    k_alpha1<<<(NN * 32 + 255) / 256, 256>>>(as1, ad1);
    k_count<<<(NE + 255) / 256, 256>>>(ei);
    k_scan<<<1, 1024>>>();
    k_self<<<(NN + 255) / 256, 256>>>();
    k_scatter<<<(NE + 255) / 256, 256>>>(ei);
    k_agg1<<<(NN * 32 + 255) / 256, 256>>>(b1);
    k_gemm_cp<256, 128><<<dim3(2, MB), 256, GSMEM_BYTES>>>(p_a1h, p_a1l, p_w2h, p_w2l, p_h2);
    k_alpha2<<<(NN * 32 + 255) / 256, 256>>>(as2, ad2);
    k_agg2<<<(NN * 32 + 255) / 256, 256>>>(b2, batch);
    k_class<<<64, 128>>>(Wc1, bc1, Wc2, bc2, out);
}

// round 17
// speedup vs baseline: 1.1986x; 1.0035x over previous
#include <cuda_runtime.h>
#include <cuda_bf16.h>
#include <math.h>
#include <stdint.h>

#define NN    30000
#define NE    960000
#define ET    (NE + NN)
#define INDIM 4527
#define KPAD1 4544
#define HOGD  4464
#define HID   128
#define NG    64

// ---------------- scratch (device globals) ----------------------------------
__device__ float g_h1[NN * 256];
__device__ float g_as1[NN * 2];
__device__ float g_ad1[NN * 2];
__device__ float g_h2[NN * HID];
__device__ float g_as2[NN];
__device__ float g_ad2[NN];
__device__ int   g_cntN[NN];
__device__ int   g_indptr[NN + 1];
__device__ int   g_cursor[NN];
__device__ int   g_srcs[ET];
__device__ float g_pool[NG * HID];
__device__ int   g_gcnt[NG];
// pre-split bf16 operands (+128 row slack so OOB tile loads stay in-bounds)
__device__ __nv_bfloat16 g_xhi[(NN + 128) * KPAD1];
__device__ __nv_bfloat16 g_xlo[(NN + 128) * KPAD1];
__device__ __nv_bfloat16 g_a1hi[(NN + 128) * 256];
__device__ __nv_bfloat16 g_a1lo[(NN + 128) * 256];
__device__ __nv_bfloat16 g_W1Thi[256 * KPAD1];
__device__ __nv_bfloat16 g_W1Tlo[256 * KPAD1];
__device__ __nv_bfloat16 g_W2Thi[128 * 256];
__device__ __nv_bfloat16 g_W2Tlo[128 * 256];

// ---------------- helpers ---------------------------------------------------
__device__ __forceinline__ uint32_t smem_u32(const void* p) {
    uint32_t a;
    asm("{ .reg .u64 t; cvta.to.shared.u64 t, %1; cvt.u32.u64 %0, t; }"
        : "=r"(a) : "l"(p));
    return a;
}
__device__ __forceinline__ float warpSum(float v) {
#pragma unroll
    for (int o = 16; o; o >>= 1) v += __shfl_xor_sync(0xffffffffu, v, o);
    return v;
}
__device__ __forceinline__ float warpMax(float v) {
#pragma unroll
    for (int o = 16; o; o >>= 1) v = fmaxf(v, __shfl_xor_sync(0xffffffffu, v, o));
    return v;
}
__device__ __forceinline__ float lrelu(float v) { return v > 0.f ? v : 0.2f * v; }

__device__ __forceinline__ void mma16816(float c[4], const uint32_t a[4],
                                         uint32_t b0, uint32_t b1) {
    asm volatile(
        "mma.sync.aligned.m16n8k16.row.col.f32.bf16.bf16.f32 "
        "{%0,%1,%2,%3}, {%4,%5,%6,%7}, {%8,%9}, {%0,%1,%2,%3};"
        : "+f"(c[0]), "+f"(c[1]), "+f"(c[2]), "+f"(c[3])
        : "r"(a[0]), "r"(a[1]), "r"(a[2]), "r"(a[3]), "r"(b0), "r"(b1));
}
#define LDSM4(r0, r1, r2, r3, addr)                                           \
    asm volatile("ldmatrix.sync.aligned.m8n8.x4.shared.b16 {%0,%1,%2,%3}, [%4];" \
                 : "=r"(r0), "=r"(r1), "=r"(r2), "=r"(r3) : "r"(addr))
#define CP16(saddr, gaddr)                                                    \
    asm volatile("cp.async.cg.shared.global [%0], [%1], 16;"                  \
                 :: "r"(saddr), "l"(gaddr))
#define CP_COMMIT() asm volatile("cp.async.commit_group;" ::: "memory")
#define CP_WAIT1()  asm volatile("cp.async.wait_group 1;" ::: "memory")

__device__ __forceinline__ unsigned packsplit(float v0, float v1, float& r0, float& r1) {
    __nv_bfloat16 h0 = __float2bfloat16(v0), h1 = __float2bfloat16(v1);
    r0 = v0 - __bfloat162float(h0);
    r1 = v1 - __bfloat162float(h1);
    unsigned short a = *(unsigned short*)&h0, b = *(unsigned short*)&h1;
    return (unsigned)a | ((unsigned)b << 16);
}
__device__ __forceinline__ unsigned packlo(float v0, float v1) {
    __nv_bfloat16 h0 = __float2bfloat16(v0), h1 = __float2bfloat16(v1);
    unsigned short a = *(unsigned short*)&h0, b = *(unsigned short*)&h1;
    return (unsigned)a | ((unsigned)b << 16);
}

// ---------------- init -------------------------------------------------------
__global__ void k_init() {
    int i = blockIdx.x * blockDim.x + threadIdx.x;
    if (i < NN) g_cntN[i] = 1;
    if (i < NG * HID) g_pool[i] = 0.f;
    if (i < NG) g_gcnt[i] = 0;
}

// ---------------- attention gate + split gated x ----------------------------
__global__ void k_attn(const float* __restrict__ x,
                       const float* __restrict__ aW,
                       const float* __restrict__ ab) {
    int n = blockIdx.x;
    int t = threadIdx.x;  // 128
    const float* xr = x + (size_t)n * INDIM;
    float p0 = 0.f, p1 = 0.f;
    for (int k = t; k < INDIM; k += 128) {
        float v = xr[k];
        p0 += v * aW[2 * k];
        p1 += v * aW[2 * k + 1];
    }
    p0 = warpSum(p0);
    p1 = warpSum(p1);
    __shared__ float s0[4], s1[4];
    __shared__ float gg[2];
    if ((t & 31) == 0) { s0[t >> 5] = p0; s1[t >> 5] = p1; }
    __syncthreads();
    if (t == 0) {
        p0 = s0[0] + s0[1] + s0[2] + s0[3] + ab[0];
        p1 = s1[0] + s1[1] + s1[2] + s1[3] + ab[1];
        float m = fmaxf(p0, p1);
        float e0 = expf(p0 - m), e1 = expf(p1 - m);
        float inv = 1.f / (e0 + e1);
        gg[0] = e0 * inv;
        gg[1] = e1 * inv;
    }
    __syncthreads();
    float g0 = gg[0], g1 = gg[1];
    uint32_t* oh = (uint32_t*)(g_xhi + (size_t)n * KPAD1);
    uint32_t* ol = (uint32_t*)(g_xlo + (size_t)n * KPAD1);
    for (int p = t; p < KPAD1 / 2; p += 128) {
        int k = 2 * p;
        float v0 = 0.f, v1 = 0.f;
        if (k < INDIM)     v0 = xr[k] * ((k < HOGD) ? g0 : g1);
        if (k + 1 < INDIM) v1 = xr[k + 1] * ((k + 1 < HOGD) ? g0 : g1);
        float r0, r1;
        oh[p] = packsplit(v0, v1, r0, r1);
        ol[p] = packlo(r0, r1);
    }
}

// ---------------- weight split (+transpose to [n][k]) -----------------------
__global__ void k_split(const float* __restrict__ W1, const float* __restrict__ W2) {
    int i = blockIdx.x * blockDim.x + threadIdx.x;
    if (i < 256 * KPAD1) {
        int n = i / KPAD1, k = i % KPAD1;
        float v = (k < INDIM) ? W1[(size_t)k * 256 + n] : 0.f;
        __nv_bfloat16 h = __float2bfloat16(v);
        g_W1Thi[i] = h;
        g_W1Tlo[i] = __float2bfloat16(v - __bfloat162float(h));
    }
    if (i < 128 * 256) {
        int n = i / 256, k = i % 256;
        float v = W2[k * 128 + n];
        __nv_bfloat16 h = __float2bfloat16(v);
        g_W2Thi[i] = h;
        g_W2Tlo[i] = __float2bfloat16(v - __bfloat162float(h));
    }
}

// ---------------- split-bf16 GEMM, 128x64 tile, 3 CTAs/SM, 3-stage ----------
// 256 threads, warp tile 32x32 (4x2 warp grid). acc=32 regs/thread.
// Stage = Ahi(8K)|Alo(8K)|Bhi(4K)|Blo(4K) = 24KB; 3 stages = 72KB.
#define PARTA2  8192
#define PARTB2  4096
#define STAGE2  (2 * PARTA2 + 2 * PARTB2)
#define GSMEM_BYTES (3 * STAGE2 + 1024)

template <int KPADT, int NTOT>
__global__ __launch_bounds__(256, 3)
void k_gemm_cp(const __nv_bfloat16* __restrict__ Ahi,
               const __nv_bfloat16* __restrict__ Alo,
               const __nv_bfloat16* __restrict__ Bhi,
               const __nv_bfloat16* __restrict__ Blo,
               float* __restrict__ C) {
    constexpr int KT = KPADT / 32;
    extern __shared__ char smraw[];
    char* smb = (char*)(((uintptr_t)smraw + 1023) & ~(uintptr_t)1023);
    const uint32_t sb = smem_u32(smb);
    const int tid = threadIdx.x;
    const int l = tid & 31, w = tid >> 5;
    const int wm = w & 3, wn = w >> 2;       // 4x2 grid, 32x32 warp tiles
    const int bn = blockIdx.x * 64;
    const int bm = blockIdx.y * 128;

    // cp.async A: row tid>>1 (0..127), chunk pair (tid&1)*2
    const int arow = tid >> 1;
    const int acp = (tid & 1) * 2;
    const int asw = (arow >> 1) & 3;
    const uint32_t as0 = (uint32_t)(arow * 64 + ((acp ^ asw) * 16));
    const uint32_t as1o = (uint32_t)(arow * 64 + (((acp + 1) ^ asw) * 16));
    // cp.async B: row tid>>2 (0..63), single chunk tid&3
    const int brow = tid >> 2;
    const int bcp = tid & 3;
    const int bsw = (brow >> 1) & 3;
    const uint32_t bs0 = (uint32_t)(brow * 64 + ((bcp ^ bsw) * 16));

    const __nv_bfloat16* aHiP = Ahi + (size_t)(bm + arow) * KPADT + acp * 8;
    const __nv_bfloat16* aLoP = Alo + (size_t)(bm + arow) * KPADT + acp * 8;
    const __nv_bfloat16* bHiP = Bhi + (size_t)(bn + brow) * KPADT + bcp * 8;
    const __nv_bfloat16* bLoP = Blo + (size_t)(bn + brow) * KPADT + bcp * 8;

    float acc[2][4][4];
#pragma unroll
    for (int i = 0; i < 2; i++)
#pragma unroll
        for (int j = 0; j < 4; j++)
#pragma unroll
            for (int q = 0; q < 4; q++) acc[i][j][q] = 0.f;

    auto cpStage = [&](int kt, int s) {
        const int k0 = kt * 32;
        uint32_t d = sb + s * STAGE2;
        CP16(d + as0,                  (const char*)(aHiP + k0));
        CP16(d + as1o,                 (const char*)(aHiP + k0 + 8));
        CP16(d + PARTA2 + as0,         (const char*)(aLoP + k0));
        CP16(d + PARTA2 + as1o,        (const char*)(aLoP + k0 + 8));
        CP16(d + 2 * PARTA2 + bs0,     (const char*)(bHiP + k0));
        CP16(d + 2 * PARTA2 + PARTB2 + bs0, (const char*)(bLoP + k0));
    };

    // LDSM address components
    const uint32_t a_roff = (uint32_t)((wm * 32 + (l & 15)) * 64);
    const int sA = ((l & 15) >> 1) & 3;
    const int aC = (l >> 4) & 1;
    const uint32_t b_rl = (uint32_t)(((l >> 4) & 1) * 8 + (l & 7));
    const uint32_t b_roff = (uint32_t)((wn * 32 + b_rl) * 64);
    const int sB = (int)((b_rl >> 1) & 3);
    const int bC = (l >> 3) & 1;

    cpStage(0, 0);
    CP_COMMIT();
    cpStage(1, 1);
    CP_COMMIT();

    int s = 0;
    for (int kt = 0; kt < KT; kt++) {
        CP_WAIT1();
        __syncthreads();
        if (kt + 2 < KT) {
            int ns = s + 2; if (ns >= 3) ns -= 3;
            cpStage(kt + 2, ns);
        }
        CP_COMMIT();

        const uint32_t stb = sb + s * STAGE2;
#pragma unroll
        for (int ks = 0; ks < 2; ks++) {
            const uint32_t ca = (uint32_t)(((2 * ks + aC) ^ sA) * 16);
            const uint32_t cb = (uint32_t)(((2 * ks + bC) ^ sB) * 16);
            uint32_t ah[2][4], al[2][4];
#pragma unroll
            for (int mt = 0; mt < 2; mt++) {
                uint32_t off = a_roff + mt * 1024 + ca;
                LDSM4(ah[mt][0], ah[mt][1], ah[mt][2], ah[mt][3], stb + off);
                LDSM4(al[mt][0], al[mt][1], al[mt][2], al[mt][3],
                      stb + PARTA2 + off);
            }
            uint32_t bh[4][2], bl[4][2];
#pragma unroll
            for (int pr = 0; pr < 2; pr++) {
                uint32_t off = b_roff + pr * 1024 + cb;
                LDSM4(bh[2 * pr][0], bh[2 * pr][1], bh[2 * pr + 1][0],
                      bh[2 * pr + 1][1], stb + 2 * PARTA2 + off);
                LDSM4(bl[2 * pr][0], bl[2 * pr][1], bl[2 * pr + 1][0],
                      bl[2 * pr + 1][1], stb + 2 * PARTA2 + PARTB2 + off);
            }
#pragma unroll
            for (int nt = 0; nt < 4; nt++)
#pragma unroll
                for (int mt = 0; mt < 2; mt++) {
                    mma16816(acc[mt][nt], ah[mt], bh[nt][0], bh[nt][1]);
                    mma16816(acc[mt][nt], ah[mt], bl[nt][0], bl[nt][1]);
                    mma16816(acc[mt][nt], al[mt], bh[nt][0], bh[nt][1]);
                }
        }
        if (++s == 3) s = 0;
    }

    const int g = l >> 2, tq = l & 3;
#pragma unroll
    for (int mt = 0; mt < 2; mt++)
#pragma unroll
        for (int nt = 0; nt < 4; nt++) {
            int m0 = bm + wm * 32 + mt * 16 + g;
            int n = bn + wn * 32 + nt * 8 + 2 * tq;
            if (m0 < NN)
                *(float2*)&C[(size_t)m0 * NTOT + n] =
                    make_float2(acc[mt][nt][0], acc[mt][nt][1]);
            if (m0 + 8 < NN)
                *(float2*)&C[(size_t)(m0 + 8) * NTOT + n] =
                    make_float2(acc[mt][nt][2], acc[mt][nt][3]);
        }
}

// ---------------- alpha layer 1 ---------------------------------------------
__global__ void k_alpha1(const float* __restrict__ as1,
                         const float* __restrict__ ad1) {
    int w = (blockIdx.x * blockDim.x + threadIdx.x) >> 5;
    int l = threadIdx.x & 31;
    if (w >= NN) return;
    const float* hr = g_h1 + (size_t)w * 256;
    float ps0 = 0, pd0 = 0, ps1 = 0, pd1 = 0;
#pragma unroll
    for (int i = 0; i < 4; i++) {
        int d = l + i * 32;
        float v0 = hr[d], v1 = hr[128 + d];
        ps0 += v0 * as1[d];        pd0 += v0 * ad1[d];
        ps1 += v1 * as1[128 + d];  pd1 += v1 * ad1[128 + d];
    }
    ps0 = warpSum(ps0); pd0 = warpSum(pd0);
    ps1 = warpSum(ps1); pd1 = warpSum(pd1);
    if (l == 0) {
        g_as1[2 * w] = ps0; g_as1[2 * w + 1] = ps1;
        g_ad1[2 * w] = pd0; g_ad1[2 * w + 1] = pd1;
    }
}

// ---------------- CSR build --------------------------------------------------
__global__ void k_count(const int* __restrict__ ei) {
    int e = blockIdx.x * blockDim.x + threadIdx.x;
    if (e < NE) atomicAdd(&g_cntN[ei[NE + e]], 1);
}

__global__ void k_scan() {
    __shared__ int sh[1024];
    int t = threadIdx.x;
    const int CH = (NN + 1023) / 1024;
    int lo = t * CH, hi = min(lo + CH, NN);
    int s = 0;
    for (int i = lo; i < hi; i++) s += g_cntN[i];
    sh[t] = s;
    __syncthreads();
    for (int o = 1; o < 1024; o <<= 1) {
        int v = (t >= o) ? sh[t - o] : 0;
        __syncthreads();
        sh[t] += v;
        __syncthreads();
    }
    int run = (t == 0) ? 0 : sh[t - 1];
    for (int i = lo; i < hi; i++) { g_indptr[i] = run; run += g_cntN[i]; }
    if (t == 1023) g_indptr[NN] = sh[1023];
}

__global__ void k_self() {
    int i = blockIdx.x * blockDim.x + threadIdx.x;
    if (i < NN) { g_cursor[i] = 1; g_srcs[g_indptr[i]] = i; }
}

__global__ void k_scatter(const int* __restrict__ ei) {
    int e = blockIdx.x * blockDim.x + threadIdx.x;
    if (e < NE) {
        int s = ei[e], d = ei[NE + e];
        int pos = g_indptr[d] + atomicAdd(&g_cursor[d], 1);
        g_srcs[pos] = s;
    }
}

// ---------------- layer-1 aggregation (online softmax, 2 gather passes) -----
__global__ void k_agg1(const float* __restrict__ b1) {
    int w = (blockIdx.x * blockDim.x + threadIdx.x) >> 5;
    int l = threadIdx.x & 31;
    if (w >= NN) return;
    int beg = g_indptr[w], end = g_indptr[w + 1];
    float ad0 = g_ad1[2 * w], ad1 = g_ad1[2 * w + 1];

    float m0 = -1e30f, d0 = 0.f, m1 = -1e30f, d1 = 0.f;
    for (int j = beg + l; j < end; j += 32) {
        int s = g_srcs[j];
        float e0 = lrelu(g_as1[2 * s] + ad0);
        float e1 = lrelu(g_as1[2 * s + 1] + ad1);
        float nm0 = fmaxf(m0, e0);
        d0 = d0 * expf(m0 - nm0) + expf(e0 - nm0);
        m0 = nm0;
        float nm1 = fmaxf(m1, e1);
        d1 = d1 * expf(m1 - nm1) + expf(e1 - nm1);
        m1 = nm1;
    }
    float M0 = warpMax(m0), M1 = warpMax(m1);
    d0 = warpSum(d0 * expf(m0 - M0));
    d1 = warpSum(d1 * expf(m1 - M1));
    m0 = M0; m1 = M1;
    float i0 = 1.f / (d0 + 1e-16f), i1 = 1.f / (d1 + 1e-16f);

    float acc[8] = {0, 0, 0, 0, 0, 0, 0, 0};
    for (int base = beg; base < end; base += 32) {
        int j = base + l;
        int s = 0; float w0 = 0.f, w1 = 0.f;
        if (j < end) {
            s = g_srcs[j];
            w0 = expf(lrelu(g_as1[2 * s] + ad0) - m0) * i0;
            w1 = expf(lrelu(g_as1[2 * s + 1] + ad1) - m1) * i1;
        }
        int cnt = min(32, end - base);
        for (int q = 0; q < cnt; q++) {
            int   sq  = __shfl_sync(0xffffffffu, s, q);
            float w0q = __shfl_sync(0xffffffffu, w0, q);
            float w1q = __shfl_sync(0xffffffffu, w1, q);
            const float* hp = g_h1 + (size_t)sq * 256 + l;
            acc[0] += w0q * hp[0];   acc[1] += w0q * hp[32];
            acc[2] += w0q * hp[64];  acc[3] += w0q * hp[96];
            acc[4] += w1q * hp[128]; acc[5] += w1q * hp[160];
            acc[6] += w1q * hp[192]; acc[7] += w1q * hp[224];
        }
    }
#pragma unroll
    for (int i = 0; i < 8; i++) {
        int d = l + i * 32;
        float v = acc[i] + b1[d];
        v = v > 0.f ? v : 0.f;
        __nv_bfloat16 h = __float2bfloat16(v);
        g_a1hi[(size_t)w * 256 + d] = h;
        g_a1lo[(size_t)w * 256 + d] = __float2bfloat16(v - __bfloat162float(h));
    }
}

// ---------------- alpha layer 2 ---------------------------------------------
__global__ void k_alpha2(const float* __restrict__ as2,
                         const float* __restrict__ ad2) {
    int w = (blockIdx.x * blockDim.x + threadIdx.x) >> 5;
    int l = threadIdx.x & 31;
    if (w >= NN) return;
    const float* hr = g_h2 + (size_t)w * 128;
    float ps = 0.f, pd = 0.f;
#pragma unroll
    for (int i = 0; i < 4; i++) {
        int d = l + i * 32;
        float v = hr[d];
        ps += v * as2[d];
        pd += v * ad2[d];
    }
    ps = warpSum(ps); pd = warpSum(pd);
    if (l == 0) { g_as2[w] = ps; g_ad2[w] = pd; }
}

// ---------------- layer-2 aggregation + pooling (online softmax) -------------
__global__ void k_agg2(const float* __restrict__ b2,
                       const int* __restrict__ batch) {
    int w = (blockIdx.x * blockDim.x + threadIdx.x) >> 5;
    int l = threadIdx.x & 31;
    if (w >= NN) return;
    int beg = g_indptr[w], end = g_indptr[w + 1];
    float ad = g_ad2[w];

    float m = -1e30f, den = 0.f;
    for (int j = beg + l; j < end; j += 32) {
        float e = lrelu(g_as2[g_srcs[j]] + ad);
        float nm = fmaxf(m, e);
        den = den * expf(m - nm) + expf(e - nm);
        m = nm;
    }
    float M = warpMax(m);
    den = warpSum(den * expf(m - M));
    m = M;
    float inv = 1.f / (den + 1e-16f);

    float acc[4] = {0, 0, 0, 0};
    for (int base = beg; base < end; base += 32) {
        int j = base + l;
        int s = 0; float ww = 0.f;
        if (j < end) {
            s = g_srcs[j];
            ww = expf(lrelu(g_as2[s] + ad) - m) * inv;
        }
        int cnt = min(32, end - base);
        for (int q = 0; q < cnt; q++) {
            int   sq = __shfl_sync(0xffffffffu, s, q);
            float wq = __shfl_sync(0xffffffffu, ww, q);
            const float* hp = g_h2 + (size_t)sq * 128 + l;
            acc[0] += wq * hp[0];  acc[1] += wq * hp[32];
            acc[2] += wq * hp[64]; acc[3] += wq * hp[96];
        }
    }
    int b = batch[w];
#pragma unroll
    for (int i = 0; i < 4; i++) {
        int d = l + i * 32;
        float v = acc[i] + b2[d];
        v = v > 0.f ? v : 0.f;
        atomicAdd(&g_pool[b * 128 + d], v);
    }
    if (l == 0) atomicAdd(&g_gcnt[b], 1);
}

// ---------------- classifier head -------------------------------------------
__global__ void k_class(const float* __restrict__ Wc1, const float* __restrict__ bc1,
                        const float* __restrict__ Wc2, const float* __restrict__ bc2,
                        float* __restrict__ out) {
    int g = blockIdx.x, t = threadIdx.x;
    __shared__ float p[128];
    __shared__ float z[64];
    float c = fmaxf((float)g_gcnt[g], 1.f);
    p[t] = g_pool[g * 128 + t] / c;
    __syncthreads();
    if (t < 64) {
        float s = bc1[t];
        for (int i = 0; i < 128; i++) s += p[i] * Wc1[i * 64 + t];
        z[t] = s > 0.f ? s : 0.f;
    }
    __syncthreads();
    if (t < 4) {
        float s = bc2[t];
        for (int i = 0; i < 64; i++) s += z[i] * Wc2[i * 4 + t];
        out[g * 4 + t] = s;
    }
}

// ---------------- launch -----------------------------------------------------
extern "C" void kernel_launch(void* const* d_in, const int* in_sizes, int n_in,
                              void* d_out, int out_size) {
    const float* x      = (const float*)d_in[0];
    const int*   ei     = (const int*)d_in[1];
    const int*   batch  = (const int*)d_in[2];
    const float* attn_W = (const float*)d_in[3];
    const float* attn_b = (const float*)d_in[4];
    const float* W1     = (const float*)d_in[5];
    const float* as1    = (const float*)d_in[6];
    const float* ad1    = (const float*)d_in[7];
    const float* b1     = (const float*)d_in[8];
    const float* W2     = (const float*)d_in[9];
    const float* as2    = (const float*)d_in[10];
    const float* ad2    = (const float*)d_in[11];
    const float* b2     = (const float*)d_in[12];
    const float* Wc1    = (const float*)d_in[13];
    const float* bc1    = (const float*)d_in[14];
    const float* Wc2    = (const float*)d_in[15];
    const float* bc2    = (const float*)d_in[16];
    float* out = (float*)d_out;

    float* p_h1;   cudaGetSymbolAddress((void**)&p_h1, g_h1);
    float* p_h2;   cudaGetSymbolAddress((void**)&p_h2, g_h2);
    __nv_bfloat16 *p_xh, *p_xl, *p_a1h, *p_a1l, *p_w1h, *p_w1l, *p_w2h, *p_w2l;
    cudaGetSymbolAddress((void**)&p_xh, g_xhi);
    cudaGetSymbolAddress((void**)&p_xl, g_xlo);
    cudaGetSymbolAddress((void**)&p_a1h, g_a1hi);
    cudaGetSymbolAddress((void**)&p_a1l, g_a1lo);
    cudaGetSymbolAddress((void**)&p_w1h, g_W1Thi);
    cudaGetSymbolAddress((void**)&p_w1l, g_W1Tlo);
    cudaGetSymbolAddress((void**)&p_w2h, g_W2Thi);
    cudaGetSymbolAddress((void**)&p_w2l, g_W2Tlo);

    cudaFuncSetAttribute(k_gemm_cp<KPAD1, 256>,
                         cudaFuncAttributeMaxDynamicSharedMemorySize, GSMEM_BYTES);
    cudaFuncSetAttribute(k_gemm_cp<256, 128>,
                         cudaFuncAttributeMaxDynamicSharedMemorySize, GSMEM_BYTES);

    const int MB = (NN + 127) / 128;  // 235

    k_init<<<(NN + 255) / 256, 256>>>();
    k_attn<<<NN, 128>>>(x, attn_W, attn_b);
    k_split<<<(256 * KPAD1 + 255) / 256, 256>>>(W1, W2);
    k_gemm_cp<KPAD1, 256><<<dim3(4, MB), 256, GSMEM_BYTES>>>(p_xh, p_xl, p_w1h, p_w1l, p_h1);
    k_alpha1<<<(NN * 32 + 255) / 256, 256>>>(as1, ad1);
    k_count<<<(NE + 255) / 256, 256>>>(ei);
    k_scan<<<1, 1024>>>();
    k_self<<<(NN + 255) / 256, 256>>>();
    k_scatter<<<(NE + 255) / 256, 256>>>(ei);
    k_agg1<<<(NN * 32 + 255) / 256, 256>>>(b1);
    k_gemm_cp<256, 128><<<dim3(2, MB), 256, GSMEM_BYTES>>>(p_a1h, p_a1l, p_w2h, p_w2l, p_h2);
    k_alpha2<<<(NN * 32 + 255) / 256, 256>>>(as2, ad2);
    k_agg2<<<(NN * 32 + 255) / 256, 256>>>(b2, batch);
    k_class<<<64, 128>>>(Wc1, bc1, Wc2, bc2, out);
}